// round 7
// baseline (speedup 1.0000x reference)
#include <cuda_runtime.h>
#include <cuda_bf16.h>
#include <math.h>
#include <stdint.h>

#define H 1024
#define I 2048
#define E 8
#define TOPK 2
#define T 4096   // B*S

// ======================= scratch (static device globals) =====================
__device__ __align__(256) int   g_counts[E];
__device__ __align__(256) float g_probsum[E];
__device__ float g_zsum;
__device__ __align__(256) int   g_list[E * T];
__device__ __align__(256) float g_wlist[E * T];

// bf16 hi/lo splits, all in NATURAL [K][N] layout (no transpose)
__device__ __align__(256) __nv_bfloat16 g_xh[(size_t)T * H];
__device__ __align__(256) __nv_bfloat16 g_xl[(size_t)T * H];
__device__ __align__(256) __nv_bfloat16 g_gh[(size_t)E * H * I];
__device__ __align__(256) __nv_bfloat16 g_gl[(size_t)E * H * I];
__device__ __align__(256) __nv_bfloat16 g_uh[(size_t)E * H * I];
__device__ __align__(256) __nv_bfloat16 g_ul[(size_t)E * H * I];
__device__ __align__(256) __nv_bfloat16 g_dh[(size_t)E * I * H];
__device__ __align__(256) __nv_bfloat16 g_dl[(size_t)E * I * H];
__device__ __align__(256) __nv_bfloat16 g_sgh[(size_t)H * I];
__device__ __align__(256) __nv_bfloat16 g_sgl[(size_t)H * I];
__device__ __align__(256) __nv_bfloat16 g_suh[(size_t)H * I];
__device__ __align__(256) __nv_bfloat16 g_sul[(size_t)H * I];
__device__ __align__(256) __nv_bfloat16 g_sdh[(size_t)I * H];
__device__ __align__(256) __nv_bfloat16 g_sdl[(size_t)I * H];
__device__ __align__(256) __nv_bfloat16 g_acth[(size_t)(E + 1) * T * I];
__device__ __align__(256) __nv_bfloat16 g_actl[(size_t)(E + 1) * T * I];

// ======================= PTX helpers ========================================
static __device__ __forceinline__ uint32_t s2u(const void* p) {
    uint32_t a;
    asm("{ .reg .u64 t; cvta.to.shared.u64 t, %1; cvt.u32.u64 %0, t; }"
        : "=r"(a) : "l"(p));
    return a;
}
static __device__ __forceinline__ void ldsm_x4(uint32_t& r0, uint32_t& r1,
                                               uint32_t& r2, uint32_t& r3,
                                               uint32_t addr) {
    asm volatile("ldmatrix.sync.aligned.m8n8.x4.shared.b16 {%0,%1,%2,%3}, [%4];"
                 : "=r"(r0), "=r"(r1), "=r"(r2), "=r"(r3) : "r"(addr));
}
static __device__ __forceinline__ void ldsm_x4t(uint32_t& r0, uint32_t& r1,
                                                uint32_t& r2, uint32_t& r3,
                                                uint32_t addr) {
    asm volatile("ldmatrix.sync.aligned.m8n8.x4.trans.shared.b16 {%0,%1,%2,%3}, [%4];"
                 : "=r"(r0), "=r"(r1), "=r"(r2), "=r"(r3) : "r"(addr));
}
static __device__ __forceinline__ void mma_bf16(float* c, const uint32_t* a,
                                                uint32_t b0, uint32_t b1) {
    asm volatile(
        "mma.sync.aligned.m16n8k16.row.col.f32.bf16.bf16.f32 "
        "{%0,%1,%2,%3}, {%4,%5,%6,%7}, {%8,%9}, {%0,%1,%2,%3};"
        : "+f"(c[0]), "+f"(c[1]), "+f"(c[2]), "+f"(c[3])
        : "r"(a[0]), "r"(a[1]), "r"(a[2]), "r"(a[3]), "r"(b0), "r"(b1));
}
static __device__ __forceinline__ void cp16(uint32_t dst, const void* src,
                                            uint32_t sz) {
    asm volatile("cp.async.cg.shared.global [%0], [%1], 16, %2;"
                 :: "r"(dst), "l"(src), "r"(sz) : "memory");
}
#define CP_COMMIT() asm volatile("cp.async.commit_group;" ::: "memory")
#define CP_WAIT1()  asm volatile("cp.async.wait_group 1;" ::: "memory")
#define CP_WAIT0()  asm volatile("cp.async.wait_group 0;" ::: "memory")

#define SWZ64(o)  ((uint32_t)(o) ^ ((((uint32_t)(o)) >> 3) & 0x30u))
#define SWZ128(o) ((uint32_t)(o) ^ ((((uint32_t)(o)) >> 3) & 0x70u))

// ======================= SMEM layouts (per stage) ===========================
// gateup stage 32KB: A_hi 8K | A_lo 8K | Bg_hi 4K | Bg_lo 4K | Bu_hi 4K | Bu_lo 4K
#define GU_A_HI   0
#define GU_A_LO   8192
#define GU_BG_HI  16384
#define GU_BG_LO  20480
#define GU_BU_HI  24576
#define GU_BU_LO  28672
#define GU_STAGE  32768
#define GU_SMEM   (1024 + 3 * GU_STAGE)
// down stage 24KB: A_hi 8K | A_lo 8K | B_hi 4K | B_lo 4K   (N=64)
#define DN_A_HI   0
#define DN_A_LO   8192
#define DN_B_HI   16384
#define DN_B_LO   20480
#define DN_STAGE  24576
#define DN_SMEM   (1024 + 3 * DN_STAGE)

// ======================= init / finalize ====================================
__global__ void init_kernel() {
    int i = threadIdx.x;
    if (i < E) { g_counts[i] = 0; g_probsum[i] = 0.f; }
    if (i == 0) g_zsum = 0.f;
}

__global__ void finalize_kernel(float* __restrict__ out) {
    if (threadIdx.x == 0) {
        float aux = 0.f;
#pragma unroll
        for (int e = 0; e < E; e++) {
            float tpe = (float)g_counts[e] / (float)(TOPK * T);
            float ppe = g_probsum[e] / (float)T;
            aux += tpe * ppe;
        }
        out[(size_t)T * H]     = (float)E * aux;
        out[(size_t)T * H + 1] = g_zsum / (float)T;
    }
}

// ======================= prep: router + x-split + out-zero + weight-split ====
static __device__ __forceinline__ void split_store(const float4 v,
                                                   __nv_bfloat16* dh,
                                                   __nv_bfloat16* dl, size_t o) {
    __nv_bfloat16 h0 = __float2bfloat16(v.x), h1 = __float2bfloat16(v.y);
    __nv_bfloat16 h2 = __float2bfloat16(v.z), h3 = __float2bfloat16(v.w);
    __nv_bfloat162 ha, hb, la, lb;
    ha.x = h0; ha.y = h1; hb.x = h2; hb.y = h3;
    la.x = __float2bfloat16(v.x - __bfloat162float(h0));
    la.y = __float2bfloat16(v.y - __bfloat162float(h1));
    lb.x = __float2bfloat16(v.z - __bfloat162float(h2));
    lb.y = __float2bfloat16(v.w - __bfloat162float(h3));
    reinterpret_cast<__nv_bfloat162*>(dh + o)[0] = ha;
    reinterpret_cast<__nv_bfloat162*>(dh + o)[1] = hb;
    reinterpret_cast<__nv_bfloat162*>(dl + o)[0] = la;
    reinterpret_cast<__nv_bfloat162*>(dl + o)[1] = lb;
}

#define GW4 ((size_t)E * H * I / 4)      // 4194304
#define SW4 ((size_t)H * I / 4)          // 524288
#define WTOT4 (3 * GW4 + 3 * SW4)        // 14155776
#define NROUTER 512
#define NWBLK (WTOT4 / 512)              // 27648

__global__ void prep_kernel(const float* __restrict__ x,
                            const float* __restrict__ rw,
                            const float* __restrict__ gw,
                            const float* __restrict__ uw,
                            const float* __restrict__ dw,
                            const float* __restrict__ sgw,
                            const float* __restrict__ suw,
                            const float* __restrict__ sdw,
                            float* __restrict__ out) {
    const int b = blockIdx.x;
    const int tid = threadIdx.x;

    if (b >= NROUTER) {
        // ---- weight split: 512 float4 per block ----
        size_t base = (size_t)(b - NROUTER) * 512 + tid;
#pragma unroll
        for (int r = 0; r < 2; r++) {
            size_t i4 = base + r * 256;
            const float* src; __nv_bfloat16 *dh, *dl; size_t loc;
            if (i4 < GW4)                { src = gw;  dh = g_gh;  dl = g_gl;  loc = i4; }
            else if (i4 < 2 * GW4)       { src = uw;  dh = g_uh;  dl = g_ul;  loc = i4 - GW4; }
            else if (i4 < 3 * GW4)       { src = dw;  dh = g_dh;  dl = g_dl;  loc = i4 - 2 * GW4; }
            else if (i4 < 3 * GW4 + SW4) { src = sgw; dh = g_sgh; dl = g_sgl; loc = i4 - 3 * GW4; }
            else if (i4 < 3 * GW4 + 2 * SW4) { src = suw; dh = g_suh; dl = g_sul; loc = i4 - 3 * GW4 - SW4; }
            else                         { src = sdw; dh = g_sdh; dl = g_sdl; loc = i4 - 3 * GW4 - 2 * SW4; }
            float4 v = reinterpret_cast<const float4*>(src)[loc];
            split_store(v, dh, dl, loc * 4);
        }
        return;
    }

    // ---- x-split for this block's 8 tokens ----
    {
        size_t base = (size_t)b * 2048;
#pragma unroll
        for (int k = 0; k < 8; k++) {
            size_t i4 = base + tid + k * 256;
            float4 v = reinterpret_cast<const float4*>(x)[i4];
            split_store(v, g_xh, g_xl, i4 * 4);
        }
    }
    // ---- zero out rows for these 8 tokens ----
    {
        float4 z4 = make_float4(0.f, 0.f, 0.f, 0.f);
        size_t base = (size_t)b * 2048;
#pragma unroll
        for (int k = 0; k < 8; k++)
            reinterpret_cast<float4*>(out)[base + tid + k * 256] = z4;
    }
    // ---- router ----
    int t = b * 8 + (tid >> 5);
    int lane = tid & 31;
    const float* xr = x + (size_t)t * H;
    float* out_logits = out + (size_t)T * H + 2;

    float acc[E];
#pragma unroll
    for (int e = 0; e < E; e++) acc[e] = 0.f;
    for (int h = lane; h < H; h += 32) {
        float xv = xr[h];
        const float4* r4 = reinterpret_cast<const float4*>(rw + (size_t)h * E);
        float4 r0 = r4[0], r1 = r4[1];
        acc[0] += xv * r0.x; acc[1] += xv * r0.y;
        acc[2] += xv * r0.z; acc[3] += xv * r0.w;
        acc[4] += xv * r1.x; acc[5] += xv * r1.y;
        acc[6] += xv * r1.z; acc[7] += xv * r1.w;
    }
#pragma unroll
    for (int e = 0; e < E; e++)
#pragma unroll
        for (int off = 16; off > 0; off >>= 1)
            acc[e] += __shfl_xor_sync(0xffffffffu, acc[e], off);

    if (lane == 0) {
        float m = acc[0];
#pragma unroll
        for (int e = 1; e < E; e++) m = fmaxf(m, acc[e]);
        float p[E], s = 0.f;
#pragma unroll
        for (int e = 0; e < E; e++) { p[e] = expf(acc[e] - m); s += p[e]; }
        float inv = 1.f / s;
#pragma unroll
        for (int e = 0; e < E; e++) out_logits[(size_t)t * E + e] = acc[e];
        float lse = m + logf(s);
        atomicAdd(&g_zsum, lse * lse);
#pragma unroll
        for (int e = 0; e < E; e++) atomicAdd(&g_probsum[e], p[e] * inv);

        int e1 = 0;
#pragma unroll
        for (int e = 1; e < E; e++) if (acc[e] > acc[e1]) e1 = e;
        int e2 = (e1 == 0) ? 1 : 0;
#pragma unroll
        for (int e = 0; e < E; e++) if (e != e1 && acc[e] > acc[e2]) e2 = e;
        float p1 = p[e1] * inv, p2 = p[e2] * inv;
        float wn = 1.f / (p1 + p2);
        int pos1 = atomicAdd(&g_counts[e1], 1);
        g_list[e1 * T + pos1] = t;  g_wlist[e1 * T + pos1] = p1 * wn;
        int pos2 = atomicAdd(&g_counts[e2], 1);
        g_list[e2 * T + pos2] = t;  g_wlist[e2 * T + pos2] = p2 * wn;
    }
}

// ======================= GEMM 1: gate+up (HMMA bf16x3, B via ldsm.trans) =====
__global__ void __launch_bounds__(256, 2) mm_gateup_kernel() {
    extern __shared__ char smem[];
    const int e = blockIdx.z;
    const int cnt = (e < E) ? g_counts[e] : T;
    const int m0 = blockIdx.y * 128;
    if (m0 >= cnt) return;
    const int n0 = blockIdx.x * 64;
    const int tid = threadIdx.x;
    const int wid = tid >> 5;
    const int lane = tid & 31;

    int* rowTok = (int*)smem;
    if (tid < 128) {
        int slot = m0 + tid;
        rowTok[tid] = (slot < cnt) ? ((e < E) ? g_list[e * T + slot] : slot) : -1;
    }
    __syncthreads();

    const uint32_t sb = s2u(smem) + 1024;

    const __nv_bfloat16* Gh = (e < E) ? g_gh + (size_t)e * H * I : g_sgh;
    const __nv_bfloat16* Gl = (e < E) ? g_gl + (size_t)e * H * I : g_sgl;
    const __nv_bfloat16* Uh = (e < E) ? g_uh + (size_t)e * H * I : g_suh;
    const __nv_bfloat16* Ul = (e < E) ? g_ul + (size_t)e * H * I : g_sul;

    // A-load mapping (gather rows, 64B k-rows, SW64)
    const int u4 = tid & 3;
    const int rb = tid >> 2;
    const int tok0 = rowTok[rb];
    const int tok1 = rowTok[rb + 64];
    const size_t aG0 = (size_t)(tok0 >= 0 ? tok0 : 0) * H + u4 * 8;
    const size_t aG1 = (size_t)(tok1 >= 0 ? tok1 : 0) * H + u4 * 8;
    const uint32_t sz0 = (tok0 >= 0) ? 16u : 0u;
    const uint32_t sz1 = (tok1 >= 0) ? 16u : 0u;
    const uint32_t dA0 = SWZ64(rb * 64 + u4 * 16);
    const uint32_t dA1 = SWZ64((rb + 64) * 64 + u4 * 16);
    // B-load mapping ([32 k-rows][128B], SW128), natural [K][N] source
    const int u8 = tid & 7;
    const int rbB = tid >> 3;            // 0..31
    const size_t bGsrc = (size_t)rbB * I + n0 + u8 * 8;
    const uint32_t dB = SWZ128(rbB * 128 + u8 * 16);

    auto load_stage = [&](int st, int c) {
        const int k0 = c * 32;
        const uint32_t bp = sb + st * GU_STAGE;
        cp16(bp + GU_A_HI + dA0, g_xh + aG0 + k0, sz0);
        cp16(bp + GU_A_LO + dA0, g_xl + aG0 + k0, sz0);
        cp16(bp + GU_A_HI + dA1, g_xh + aG1 + k0, sz1);
        cp16(bp + GU_A_LO + dA1, g_xl + aG1 + k0, sz1);
        size_t bo = bGsrc + (size_t)k0 * I;
        cp16(bp + GU_BG_HI + dB, Gh + bo, 16);
        cp16(bp + GU_BG_LO + dB, Gl + bo, 16);
        cp16(bp + GU_BU_HI + dB, Uh + bo, 16);
        cp16(bp + GU_BU_LO + dB, Ul + bo, 16);
    };

    float accG[4][2][4], accU[4][2][4];
#pragma unroll
    for (int i = 0; i < 4; i++)
#pragma unroll
        for (int j = 0; j < 2; j++)
#pragma unroll
            for (int q = 0; q < 4; q++) { accG[i][j][q] = 0.f; accU[i][j][q] = 0.f; }

    const int mw = (wid & 1) * 64;
    const int nw = (wid >> 1) * 16;
    const int arow_off = ((lane >> 3) & 1) * 8 + (lane & 7);
    const int akb_off = (lane >> 4) * 16;
    // B trans-ldsm lane mapping: k_local x n_octet
    const int kloc = (lane & 7) + ((lane >> 3) & 1) * 8;
    const int noff = (lane >> 4) * 8;

    uint32_t aoff[4][2], boff[2];
#pragma unroll
    for (int i = 0; i < 4; i++)
#pragma unroll
        for (int kk = 0; kk < 2; kk++)
            aoff[i][kk] = SWZ64((mw + i * 16 + arow_off) * 64 + kk * 32 + akb_off);
#pragma unroll
    for (int kk = 0; kk < 2; kk++)
        boff[kk] = SWZ128((kk * 16 + kloc) * 128 + (nw + noff) * 2);

    auto compute_stage = [&](int st, bool doLoad, int lstage, int lc) {
        const uint32_t bp = sb + st * GU_STAGE;
#pragma unroll
        for (int kk = 0; kk < 2; kk++) {
            uint32_t a[4][4];
            uint32_t gh[4], gl[4], uh[4], ul[4];
            ldsm_x4t(gh[0], gh[1], gh[2], gh[3], bp + GU_BG_HI + boff[kk]);
            ldsm_x4t(gl[0], gl[1], gl[2], gl[3], bp + GU_BG_LO + boff[kk]);
            ldsm_x4t(uh[0], uh[1], uh[2], uh[3], bp + GU_BU_HI + boff[kk]);
            ldsm_x4t(ul[0], ul[1], ul[2], ul[3], bp + GU_BU_LO + boff[kk]);
#pragma unroll
            for (int i = 0; i < 4; i++)
                ldsm_x4(a[i][0], a[i][1], a[i][2], a[i][3], bp + GU_A_HI + aoff[i][kk]);
            if (kk == 0 && doLoad) { load_stage(lstage, lc); CP_COMMIT(); }
#pragma unroll
            for (int i = 0; i < 4; i++) {
                mma_bf16(accG[i][0], a[i], gh[0], gh[1]);
                mma_bf16(accG[i][1], a[i], gh[2], gh[3]);
                mma_bf16(accU[i][0], a[i], uh[0], uh[1]);
                mma_bf16(accU[i][1], a[i], uh[2], uh[3]);
            }
#pragma unroll
            for (int i = 0; i < 4; i++) {
                mma_bf16(accG[i][0], a[i], gl[0], gl[1]);
                mma_bf16(accG[i][1], a[i], gl[2], gl[3]);
                mma_bf16(accU[i][0], a[i], ul[0], ul[1]);
                mma_bf16(accU[i][1], a[i], ul[2], ul[3]);
            }
#pragma unroll
            for (int i = 0; i < 4; i++)
                ldsm_x4(a[i][0], a[i][1], a[i][2], a[i][3], bp + GU_A_LO + aoff[i][kk]);
#pragma unroll
            for (int i = 0; i < 4; i++) {
                mma_bf16(accG[i][0], a[i], gh[0], gh[1]);
                mma_bf16(accG[i][1], a[i], gh[2], gh[3]);
                mma_bf16(accU[i][0], a[i], uh[0], uh[1]);
                mma_bf16(accU[i][1], a[i], uh[2], uh[3]);
            }
        }
    };

    const int NC = H / 32;
    load_stage(0, 0); CP_COMMIT();
    load_stage(1, 1); CP_COMMIT();
    int st = 0;
    for (int c = 0; c < NC; c++) {
        if (c < NC - 1) CP_WAIT1(); else CP_WAIT0();
        __syncthreads();
        int ls = st + 2; if (ls >= 3) ls -= 3;
        compute_stage(st, c + 2 < NC, ls, c + 2);
        if (++st == 3) st = 0;
    }

    const int r4 = lane >> 2;
    const int cp2 = (lane & 3) * 2;
#pragma unroll
    for (int i = 0; i < 4; i++)
#pragma unroll
        for (int hh = 0; hh < 2; hh++) {
            int slot = m0 + mw + i * 16 + r4 + hh * 8;
            if (slot >= cnt) continue;
#pragma unroll
            for (int j = 0; j < 2; j++) {
                float g0 = accG[i][j][hh * 2 + 0], g1 = accG[i][j][hh * 2 + 1];
                float u0 = accU[i][j][hh * 2 + 0], u1 = accU[i][j][hh * 2 + 1];
                float v0 = g0 / (1.f + __expf(-g0)) * u0;
                float v1 = g1 / (1.f + __expf(-g1)) * u1;
                __nv_bfloat16 h0 = __float2bfloat16(v0), h1 = __float2bfloat16(v1);
                __nv_bfloat162 hp; hp.x = h0; hp.y = h1;
                __nv_bfloat162 lp;
                lp.x = __float2bfloat16(v0 - __bfloat162float(h0));
                lp.y = __float2bfloat16(v1 - __bfloat162float(h1));
                size_t ai = (size_t)e * T * I + (size_t)slot * I + n0 + nw + j * 8 + cp2;
                *reinterpret_cast<__nv_bfloat162*>(g_acth + ai) = hp;
                *reinterpret_cast<__nv_bfloat162*>(g_actl + ai) = lp;
            }
        }
}

// ======================= GEMM 2: down (fused routed+shared, N=64) ============
__global__ void __launch_bounds__(256, 2) mm_down_kernel(float* __restrict__ out) {
    extern __shared__ char smem[];
    const int ez = blockIdx.z;           // 0..7 routed, 8 shared
    const bool routed = (ez < E);
    const int cnt = routed ? g_counts[ez] : T;
    const int m0 = blockIdx.y * 128;
    if (m0 >= cnt) return;
    const int n0 = blockIdx.x * 64;
    const int tid = threadIdx.x;
    const int wid = tid >> 5;
    const int lane = tid & 31;

    int* tokSm = (int*)smem;
    float* wSm = (float*)(smem + 512);
    if (tid < 128) {
        int slot = m0 + tid;
        if (routed) {
            tokSm[tid] = (slot < cnt) ? g_list[ez * T + slot] : 0;
            wSm[tid]   = (slot < cnt) ? g_wlist[ez * T + slot] : 0.f;
        } else {
            tokSm[tid] = slot;
            wSm[tid]   = 1.f;
        }
    }
    __syncthreads();

    const uint32_t sb = s2u(smem) + 1024;

    const __nv_bfloat16* Bh = routed ? g_dh + (size_t)ez * I * H : g_sdh;
    const __nv_bfloat16* Bl = routed ? g_dl + (size_t)ez * I * H : g_sdl;
    const __nv_bfloat16* Ah = g_acth + (size_t)ez * T * I;
    const __nv_bfloat16* Al = g_actl + (size_t)ez * T * I;

    const int u4 = tid & 3;
    const int rb = tid >> 2;
    const int slot0 = m0 + rb;
    const int slot1 = m0 + rb + 64;
    const size_t aO0 = (size_t)(slot0 < cnt ? slot0 : 0) * I + u4 * 8;
    const size_t aO1 = (size_t)(slot1 < cnt ? slot1 : 0) * I + u4 * 8;
    const uint32_t sz0 = (slot0 < cnt) ? 16u : 0u;
    const uint32_t sz1 = (slot1 < cnt) ? 16u : 0u;
    const uint32_t dA0 = SWZ64(rb * 64 + u4 * 16);
    const uint32_t dA1 = SWZ64((rb + 64) * 64 + u4 * 16);
    const int u8 = tid & 7;
    const int rbB = tid >> 3;
    const size_t bSrc = (size_t)rbB * H + n0 + u8 * 8;
    const uint32_t dB = SWZ128(rbB * 128 + u8 * 16);

    auto load_stage = [&](int st, int c) {
        const int k0 = c * 32;
        const uint32_t bp = sb + st * DN_STAGE;
        cp16(bp + DN_A_HI + dA0, Ah + aO0 + k0, sz0);
        cp16(bp + DN_A_LO + dA0, Al + aO0 + k0, sz0);
        cp16(bp + DN_A_HI + dA1, Ah + aO1 + k0, sz1);
        cp16(bp + DN_A_LO + dA1, Al + aO1 + k0, sz1);
        size_t bo = bSrc + (size_t)k0 * H;
        cp16(bp + DN_B_HI + dB, Bh + bo, 16);
        cp16(bp + DN_B_LO + dB, Bl + bo, 16);
    };

    float acc[4][2][4];
#pragma unroll
    for (int i = 0; i < 4; i++)
#pragma unroll
        for (int j = 0; j < 2; j++)
#pragma unroll
            for (int q = 0; q < 4; q++) acc[i][j][q] = 0.f;

    const int mw = (wid & 1) * 64;
    const int nw = (wid >> 1) * 16;
    const int arow_off = ((lane >> 3) & 1) * 8 + (lane & 7);
    const int akb_off = (lane >> 4) * 16;
    const int kloc = (lane & 7) + ((lane >> 3) & 1) * 8;
    const int noff = (lane >> 4) * 8;

    uint32_t aoff[4][2], boff[2];
#pragma unroll
    for (int i = 0; i < 4; i++)
#pragma unroll
        for (int kk = 0; kk < 2; kk++)
            aoff[i][kk] = SWZ64((mw + i * 16 + arow_off) * 64 + kk * 32 + akb_off);
#pragma unroll
    for (int kk = 0; kk < 2; kk++)
        boff[kk] = SWZ128((kk * 16 + kloc) * 128 + (nw + noff) * 2);

    auto compute_stage = [&](int st, bool doLoad, int lstage, int lc) {
        const uint32_t bp = sb + st * DN_STAGE;
#pragma unroll
        for (int kk = 0; kk < 2; kk++) {
            uint32_t a[4][4];
            uint32_t bh[4], bl[4];
            ldsm_x4t(bh[0], bh[1], bh[2], bh[3], bp + DN_B_HI + boff[kk]);
            ldsm_x4t(bl[0], bl[1], bl[2], bl[3], bp + DN_B_LO + boff[kk]);
#pragma unroll
            for (int i = 0; i < 4; i++)
                ldsm_x4(a[i][0], a[i][1], a[i][2], a[i][3], bp + DN_A_HI + aoff[i][kk]);
            if (kk == 0 && doLoad) { load_stage(lstage, lc); CP_COMMIT(); }
#pragma unroll
            for (int i = 0; i < 4; i++) {
                mma_bf16(acc[i][0], a[i], bh[0], bh[1]);
                mma_bf16(acc[i][1], a[i], bh[2], bh[3]);
            }
#pragma unroll
            for (int i = 0; i < 4; i++) {
                mma_bf16(acc[i][0], a[i], bl[0], bl[1]);
                mma_bf16(acc[i][1], a[i], bl[2], bl[3]);
            }
#pragma unroll
            for (int i = 0; i < 4; i++)
                ldsm_x4(a[i][0], a[i][1], a[i][2], a[i][3], bp + DN_A_LO + aoff[i][kk]);
#pragma unroll
            for (int i = 0; i < 4; i++) {
                mma_bf16(acc[i][0], a[i], bh[0], bh[1]);
                mma_bf16(acc[i][1], a[i], bh[2], bh[3]);
            }
        }
    };

    const int NC = I / 32;
    load_stage(0, 0); CP_COMMIT();
    load_stage(1, 1); CP_COMMIT();
    int st = 0;
    for (int c = 0; c < NC; c++) {
        if (c < NC - 1) CP_WAIT1(); else CP_WAIT0();
        __syncthreads();
        int ls = st + 2; if (ls >= 3) ls -= 3;
        compute_stage(st, c + 2 < NC, ls, c + 2);
        if (++st == 3) st = 0;
    }

    const int r4 = lane >> 2;
    const int cp2 = (lane & 3) * 2;
#pragma unroll
    for (int i = 0; i < 4; i++)
#pragma unroll
        for (int hh = 0; hh < 2; hh++) {
            int row = mw + i * 16 + r4 + hh * 8;
            int slot = m0 + row;
            if (slot >= cnt) continue;
            int tok = tokSm[row];
            float w = wSm[row];
            float* dst = out + (size_t)tok * H;
#pragma unroll
            for (int j = 0; j < 2; j++) {
                int col = n0 + nw + j * 8 + cp2;
                atomicAdd(&dst[col],     w * acc[i][j][hh * 2 + 0]);
                atomicAdd(&dst[col + 1], w * acc[i][j][hh * 2 + 1]);
            }
        }
}

// ======================= launch =============================================
extern "C" void kernel_launch(void* const* d_in, const int* in_sizes, int n_in,
                              void* d_out, int out_size) {
    const float* x   = (const float*)d_in[0];
    const float* rw  = (const float*)d_in[1];
    const float* gw  = (const float*)d_in[2];
    const float* uw  = (const float*)d_in[3];
    const float* dw  = (const float*)d_in[4];
    const float* sgw = (const float*)d_in[5];
    const float* suw = (const float*)d_in[6];
    const float* sdw = (const float*)d_in[7];
    float* out = (float*)d_out;

    cudaFuncSetAttribute(mm_gateup_kernel,
                         cudaFuncAttributeMaxDynamicSharedMemorySize, GU_SMEM);
    cudaFuncSetAttribute(mm_down_kernel,
                         cudaFuncAttributeMaxDynamicSharedMemorySize, DN_SMEM);

    init_kernel<<<1, 32>>>();
    prep_kernel<<<NROUTER + NWBLK, 256>>>(x, rw, gw, uw, dw, sgw, suw, sdw, out);
    mm_gateup_kernel<<<dim3(I / 64, T / 128, E + 1), 256, GU_SMEM>>>();
    mm_down_kernel<<<dim3(H / 64, T / 128, E + 1), 256, DN_SMEM>>>(out);
    finalize_kernel<<<1, 32>>>(out);
}

// round 8
// speedup vs baseline: 1.3449x; 1.3449x over previous
#include <cuda_runtime.h>
#include <cuda_fp16.h>
#include <math.h>
#include <stdint.h>

#define H 1024
#define I 2048
#define E 8
#define TOPK 2
#define T 4096   // B*S

// ======================= scratch (static device globals) =====================
__device__ __align__(256) int   g_counts[E];
__device__ __align__(256) float g_probsum[E];
__device__ float g_zsum;
__device__ __align__(256) int   g_list[E * T];
__device__ __align__(256) float g_wlist[E * T];

// activations: fp16 hi/lo split (exact). weights: single fp16 (rounded).
__device__ __align__(256) __half g_xh[(size_t)T * H];
__device__ __align__(256) __half g_xl[(size_t)T * H];
__device__ __align__(256) __half g_g[(size_t)E * H * I];
__device__ __align__(256) __half g_u[(size_t)E * H * I];
__device__ __align__(256) __half g_d[(size_t)E * I * H];
__device__ __align__(256) __half g_sg[(size_t)H * I];
__device__ __align__(256) __half g_su[(size_t)H * I];
__device__ __align__(256) __half g_sd[(size_t)I * H];
__device__ __align__(256) __half g_acth[(size_t)(E + 1) * T * I];
__device__ __align__(256) __half g_actl[(size_t)(E + 1) * T * I];

// ======================= PTX helpers ========================================
static __device__ __forceinline__ uint32_t s2u(const void* p) {
    uint32_t a;
    asm("{ .reg .u64 t; cvta.to.shared.u64 t, %1; cvt.u32.u64 %0, t; }"
        : "=r"(a) : "l"(p));
    return a;
}
static __device__ __forceinline__ void ldsm_x4(uint32_t& r0, uint32_t& r1,
                                               uint32_t& r2, uint32_t& r3,
                                               uint32_t addr) {
    asm volatile("ldmatrix.sync.aligned.m8n8.x4.shared.b16 {%0,%1,%2,%3}, [%4];"
                 : "=r"(r0), "=r"(r1), "=r"(r2), "=r"(r3) : "r"(addr));
}
static __device__ __forceinline__ void ldsm_x4t(uint32_t& r0, uint32_t& r1,
                                                uint32_t& r2, uint32_t& r3,
                                                uint32_t addr) {
    asm volatile("ldmatrix.sync.aligned.m8n8.x4.trans.shared.b16 {%0,%1,%2,%3}, [%4];"
                 : "=r"(r0), "=r"(r1), "=r"(r2), "=r"(r3) : "r"(addr));
}
static __device__ __forceinline__ void mma_f16(float* c, const uint32_t* a,
                                               uint32_t b0, uint32_t b1) {
    asm volatile(
        "mma.sync.aligned.m16n8k16.row.col.f32.f16.f16.f32 "
        "{%0,%1,%2,%3}, {%4,%5,%6,%7}, {%8,%9}, {%0,%1,%2,%3};"
        : "+f"(c[0]), "+f"(c[1]), "+f"(c[2]), "+f"(c[3])
        : "r"(a[0]), "r"(a[1]), "r"(a[2]), "r"(a[3]), "r"(b0), "r"(b1));
}
static __device__ __forceinline__ void cp16(uint32_t dst, const void* src,
                                            uint32_t sz) {
    asm volatile("cp.async.cg.shared.global [%0], [%1], 16, %2;"
                 :: "r"(dst), "l"(src), "r"(sz) : "memory");
}
#define CP_COMMIT() asm volatile("cp.async.commit_group;" ::: "memory")
#define CP_WAIT1()  asm volatile("cp.async.wait_group 1;" ::: "memory")
#define CP_WAIT0()  asm volatile("cp.async.wait_group 0;" ::: "memory")

#define SWZ64(o)  ((uint32_t)(o) ^ ((((uint32_t)(o)) >> 3) & 0x30u))
#define SWZ128(o) ((uint32_t)(o) ^ ((((uint32_t)(o)) >> 3) & 0x70u))

// ======================= SMEM layouts (per stage) ===========================
// gateup stage 24KB: A_hi 8K | A_lo 8K | Bg 4K | Bu 4K
#define GU_A_HI   0
#define GU_A_LO   8192
#define GU_BG     16384
#define GU_BU     20480
#define GU_STAGE  24576
#define GU_SMEM   (1024 + 3 * GU_STAGE)
// down stage 20KB: A_hi 8K | A_lo 8K | B 4K   (N=64)
#define DN_A_HI   0
#define DN_A_LO   8192
#define DN_B      16384
#define DN_STAGE  20480
#define DN_SMEM   (1024 + 3 * DN_STAGE)

// ======================= init / finalize ====================================
__global__ void init_kernel() {
    int i = threadIdx.x;
    if (i < E) { g_counts[i] = 0; g_probsum[i] = 0.f; }
    if (i == 0) g_zsum = 0.f;
}

__global__ void finalize_kernel(float* __restrict__ out) {
    if (threadIdx.x == 0) {
        float aux = 0.f;
#pragma unroll
        for (int e = 0; e < E; e++) {
            float tpe = (float)g_counts[e] / (float)(TOPK * T);
            float ppe = g_probsum[e] / (float)T;
            aux += tpe * ppe;
        }
        out[(size_t)T * H]     = (float)E * aux;
        out[(size_t)T * H + 1] = g_zsum / (float)T;
    }
}

// ======================= prep ===============================================
static __device__ __forceinline__ void split_store_x(const float4 v,
                                                     __half* dh, __half* dl,
                                                     size_t o) {
    __half h0 = __float2half(v.x), h1 = __float2half(v.y);
    __half h2 = __float2half(v.z), h3 = __float2half(v.w);
    __half2 ha, hb, la, lb;
    ha.x = h0; ha.y = h1; hb.x = h2; hb.y = h3;
    la.x = __float2half(v.x - __half2float(h0));
    la.y = __float2half(v.y - __half2float(h1));
    lb.x = __float2half(v.z - __half2float(h2));
    lb.y = __float2half(v.w - __half2float(h3));
    reinterpret_cast<__half2*>(dh + o)[0] = ha;
    reinterpret_cast<__half2*>(dh + o)[1] = hb;
    reinterpret_cast<__half2*>(dl + o)[0] = la;
    reinterpret_cast<__half2*>(dl + o)[1] = lb;
}
static __device__ __forceinline__ void round_store_w(const float4 v,
                                                     __half* dh, size_t o) {
    __half2 a, b;
    a.x = __float2half(v.x); a.y = __float2half(v.y);
    b.x = __float2half(v.z); b.y = __float2half(v.w);
    reinterpret_cast<__half2*>(dh + o)[0] = a;
    reinterpret_cast<__half2*>(dh + o)[1] = b;
}

#define GW4 ((size_t)E * H * I / 4)      // 4194304
#define SW4 ((size_t)H * I / 4)          // 524288
#define WTOT4 (3 * GW4 + 3 * SW4)        // 14155776
#define NROUTER 512
#define NWBLK (WTOT4 / 512)              // 27648

__global__ void prep_kernel(const float* __restrict__ x,
                            const float* __restrict__ rw,
                            const float* __restrict__ gw,
                            const float* __restrict__ uw,
                            const float* __restrict__ dw,
                            const float* __restrict__ sgw,
                            const float* __restrict__ suw,
                            const float* __restrict__ sdw,
                            float* __restrict__ out) {
    const int b = blockIdx.x;
    const int tid = threadIdx.x;

    if (b >= NROUTER) {
        size_t base = (size_t)(b - NROUTER) * 512 + tid;
#pragma unroll
        for (int r = 0; r < 2; r++) {
            size_t i4 = base + r * 256;
            const float* src; __half* dh; size_t loc;
            if (i4 < GW4)                { src = gw;  dh = g_g;  loc = i4; }
            else if (i4 < 2 * GW4)       { src = uw;  dh = g_u;  loc = i4 - GW4; }
            else if (i4 < 3 * GW4)       { src = dw;  dh = g_d;  loc = i4 - 2 * GW4; }
            else if (i4 < 3 * GW4 + SW4) { src = sgw; dh = g_sg; loc = i4 - 3 * GW4; }
            else if (i4 < 3 * GW4 + 2 * SW4) { src = suw; dh = g_su; loc = i4 - 3 * GW4 - SW4; }
            else                         { src = sdw; dh = g_sd; loc = i4 - 3 * GW4 - 2 * SW4; }
            float4 v = reinterpret_cast<const float4*>(src)[loc];
            round_store_w(v, dh, loc * 4);
        }
        return;
    }

    // ---- x-split + zero out rows for this block's 8 tokens ----
    {
        size_t base = (size_t)b * 2048;
        float4 z4 = make_float4(0.f, 0.f, 0.f, 0.f);
#pragma unroll
        for (int k = 0; k < 8; k++) {
            size_t i4 = base + tid + k * 256;
            float4 v = reinterpret_cast<const float4*>(x)[i4];
            split_store_x(v, g_xh, g_xl, i4 * 4);
            reinterpret_cast<float4*>(out)[i4] = z4;
        }
    }
    // ---- router ----
    int t = b * 8 + (tid >> 5);
    int lane = tid & 31;
    const float* xr = x + (size_t)t * H;
    float* out_logits = out + (size_t)T * H + 2;

    float acc[E];
#pragma unroll
    for (int e = 0; e < E; e++) acc[e] = 0.f;
    for (int h = lane; h < H; h += 32) {
        float xv = xr[h];
        const float4* r4 = reinterpret_cast<const float4*>(rw + (size_t)h * E);
        float4 r0 = r4[0], r1 = r4[1];
        acc[0] += xv * r0.x; acc[1] += xv * r0.y;
        acc[2] += xv * r0.z; acc[3] += xv * r0.w;
        acc[4] += xv * r1.x; acc[5] += xv * r1.y;
        acc[6] += xv * r1.z; acc[7] += xv * r1.w;
    }
#pragma unroll
    for (int e = 0; e < E; e++)
#pragma unroll
        for (int off = 16; off > 0; off >>= 1)
            acc[e] += __shfl_xor_sync(0xffffffffu, acc[e], off);

    if (lane == 0) {
        float m = acc[0];
#pragma unroll
        for (int e = 1; e < E; e++) m = fmaxf(m, acc[e]);
        float p[E], s = 0.f;
#pragma unroll
        for (int e = 0; e < E; e++) { p[e] = expf(acc[e] - m); s += p[e]; }
        float inv = 1.f / s;
#pragma unroll
        for (int e = 0; e < E; e++) out_logits[(size_t)t * E + e] = acc[e];
        float lse = m + logf(s);
        atomicAdd(&g_zsum, lse * lse);
#pragma unroll
        for (int e = 0; e < E; e++) atomicAdd(&g_probsum[e], p[e] * inv);

        int e1 = 0;
#pragma unroll
        for (int e = 1; e < E; e++) if (acc[e] > acc[e1]) e1 = e;
        int e2 = (e1 == 0) ? 1 : 0;
#pragma unroll
        for (int e = 0; e < E; e++) if (e != e1 && acc[e] > acc[e2]) e2 = e;
        float p1 = p[e1] * inv, p2 = p[e2] * inv;
        float wn = 1.f / (p1 + p2);
        int pos1 = atomicAdd(&g_counts[e1], 1);
        g_list[e1 * T + pos1] = t;  g_wlist[e1 * T + pos1] = p1 * wn;
        int pos2 = atomicAdd(&g_counts[e2], 1);
        g_list[e2 * T + pos2] = t;  g_wlist[e2 * T + pos2] = p2 * wn;
    }
}

// ======================= GEMM 1: gate+up (HMMA fp16x2) =======================
__global__ void __launch_bounds__(256, 2) mm_gateup_kernel() {
    extern __shared__ char smem[];
    const int e = blockIdx.z;
    const int cnt = (e < E) ? g_counts[e] : T;
    const int m0 = blockIdx.y * 128;
    if (m0 >= cnt) return;
    const int n0 = blockIdx.x * 64;
    const int tid = threadIdx.x;
    const int wid = tid >> 5;
    const int lane = tid & 31;

    int* rowTok = (int*)smem;
    if (tid < 128) {
        int slot = m0 + tid;
        rowTok[tid] = (slot < cnt) ? ((e < E) ? g_list[e * T + slot] : slot) : -1;
    }
    __syncthreads();

    const uint32_t sb = s2u(smem) + 1024;

    const __half* Gw = (e < E) ? g_g + (size_t)e * H * I : g_sg;
    const __half* Uw = (e < E) ? g_u + (size_t)e * H * I : g_su;

    const int u4 = tid & 3;
    const int rb = tid >> 2;
    const int tok0 = rowTok[rb];
    const int tok1 = rowTok[rb + 64];
    const size_t aG0 = (size_t)(tok0 >= 0 ? tok0 : 0) * H + u4 * 8;
    const size_t aG1 = (size_t)(tok1 >= 0 ? tok1 : 0) * H + u4 * 8;
    const uint32_t sz0 = (tok0 >= 0) ? 16u : 0u;
    const uint32_t sz1 = (tok1 >= 0) ? 16u : 0u;
    const uint32_t dA0 = SWZ64(rb * 64 + u4 * 16);
    const uint32_t dA1 = SWZ64((rb + 64) * 64 + u4 * 16);
    const int u8 = tid & 7;
    const int rbB = tid >> 3;
    const size_t bGsrc = (size_t)rbB * I + n0 + u8 * 8;
    const uint32_t dB = SWZ128(rbB * 128 + u8 * 16);

    auto load_stage = [&](int st, int c) {
        const int k0 = c * 32;
        const uint32_t bp = sb + st * GU_STAGE;
        cp16(bp + GU_A_HI + dA0, g_xh + aG0 + k0, sz0);
        cp16(bp + GU_A_LO + dA0, g_xl + aG0 + k0, sz0);
        cp16(bp + GU_A_HI + dA1, g_xh + aG1 + k0, sz1);
        cp16(bp + GU_A_LO + dA1, g_xl + aG1 + k0, sz1);
        size_t bo = bGsrc + (size_t)k0 * I;
        cp16(bp + GU_BG + dB, Gw + bo, 16);
        cp16(bp + GU_BU + dB, Uw + bo, 16);
    };

    float accG[4][2][4], accU[4][2][4];
#pragma unroll
    for (int i = 0; i < 4; i++)
#pragma unroll
        for (int j = 0; j < 2; j++)
#pragma unroll
            for (int q = 0; q < 4; q++) { accG[i][j][q] = 0.f; accU[i][j][q] = 0.f; }

    const int mw = (wid & 1) * 64;
    const int nw = (wid >> 1) * 16;
    const int arow_off = ((lane >> 3) & 1) * 8 + (lane & 7);
    const int akb_off = (lane >> 4) * 16;
    const int kloc = (lane & 7) + ((lane >> 3) & 1) * 8;
    const int noff = (lane >> 4) * 8;

    uint32_t aoff[4][2], boff[2];
#pragma unroll
    for (int i = 0; i < 4; i++)
#pragma unroll
        for (int kk = 0; kk < 2; kk++)
            aoff[i][kk] = SWZ64((mw + i * 16 + arow_off) * 64 + kk * 32 + akb_off);
#pragma unroll
    for (int kk = 0; kk < 2; kk++)
        boff[kk] = SWZ128((kk * 16 + kloc) * 128 + (nw + noff) * 2);

    auto compute_stage = [&](int st, bool doLoad, int lstage, int lc) {
        const uint32_t bp = sb + st * GU_STAGE;
#pragma unroll
        for (int kk = 0; kk < 2; kk++) {
            uint32_t a[4][4];
            uint32_t gb[4], ub[4];
            ldsm_x4t(gb[0], gb[1], gb[2], gb[3], bp + GU_BG + boff[kk]);
            ldsm_x4t(ub[0], ub[1], ub[2], ub[3], bp + GU_BU + boff[kk]);
#pragma unroll
            for (int i = 0; i < 4; i++)
                ldsm_x4(a[i][0], a[i][1], a[i][2], a[i][3], bp + GU_A_HI + aoff[i][kk]);
            if (kk == 0 && doLoad) { load_stage(lstage, lc); CP_COMMIT(); }
#pragma unroll
            for (int i = 0; i < 4; i++) {
                mma_f16(accG[i][0], a[i], gb[0], gb[1]);
                mma_f16(accG[i][1], a[i], gb[2], gb[3]);
                mma_f16(accU[i][0], a[i], ub[0], ub[1]);
                mma_f16(accU[i][1], a[i], ub[2], ub[3]);
            }
#pragma unroll
            for (int i = 0; i < 4; i++)
                ldsm_x4(a[i][0], a[i][1], a[i][2], a[i][3], bp + GU_A_LO + aoff[i][kk]);
#pragma unroll
            for (int i = 0; i < 4; i++) {
                mma_f16(accG[i][0], a[i], gb[0], gb[1]);
                mma_f16(accG[i][1], a[i], gb[2], gb[3]);
                mma_f16(accU[i][0], a[i], ub[0], ub[1]);
                mma_f16(accU[i][1], a[i], ub[2], ub[3]);
            }
        }
    };

    const int NC = H / 32;
    load_stage(0, 0); CP_COMMIT();
    load_stage(1, 1); CP_COMMIT();
    int st = 0;
    for (int c = 0; c < NC; c++) {
        if (c < NC - 1) CP_WAIT1(); else CP_WAIT0();
        __syncthreads();
        int ls = st + 2; if (ls >= 3) ls -= 3;
        compute_stage(st, c + 2 < NC, ls, c + 2);
        if (++st == 3) st = 0;
    }

    const int r4 = lane >> 2;
    const int cp2 = (lane & 3) * 2;
#pragma unroll
    for (int i = 0; i < 4; i++)
#pragma unroll
        for (int hh = 0; hh < 2; hh++) {
            int slot = m0 + mw + i * 16 + r4 + hh * 8;
            if (slot >= cnt) continue;
#pragma unroll
            for (int j = 0; j < 2; j++) {
                float g0 = accG[i][j][hh * 2 + 0], g1 = accG[i][j][hh * 2 + 1];
                float u0 = accU[i][j][hh * 2 + 0], u1 = accU[i][j][hh * 2 + 1];
                float v0 = g0 / (1.f + __expf(-g0)) * u0;
                float v1 = g1 / (1.f + __expf(-g1)) * u1;
                __half h0 = __float2half(v0), h1 = __float2half(v1);
                __half2 hp; hp.x = h0; hp.y = h1;
                __half2 lp;
                lp.x = __float2half(v0 - __half2float(h0));
                lp.y = __float2half(v1 - __half2float(h1));
                size_t ai = (size_t)e * T * I + (size_t)slot * I + n0 + nw + j * 8 + cp2;
                *reinterpret_cast<__half2*>(g_acth + ai) = hp;
                *reinterpret_cast<__half2*>(g_actl + ai) = lp;
            }
        }
}

// ======================= GEMM 2: down (fused routed+shared, fp16x2) ==========
__global__ void __launch_bounds__(256, 2) mm_down_kernel(float* __restrict__ out) {
    extern __shared__ char smem[];
    const int ez = blockIdx.z;           // 0..7 routed, 8 shared
    const bool routed = (ez < E);
    const int cnt = routed ? g_counts[ez] : T;
    const int m0 = blockIdx.y * 128;
    if (m0 >= cnt) return;
    const int n0 = blockIdx.x * 64;
    const int tid = threadIdx.x;
    const int wid = tid >> 5;
    const int lane = tid & 31;

    int* tokSm = (int*)smem;
    float* wSm = (float*)(smem + 512);
    if (tid < 128) {
        int slot = m0 + tid;
        if (routed) {
            tokSm[tid] = (slot < cnt) ? g_list[ez * T + slot] : 0;
            wSm[tid]   = (slot < cnt) ? g_wlist[ez * T + slot] : 0.f;
        } else {
            tokSm[tid] = slot;
            wSm[tid]   = 1.f;
        }
    }
    __syncthreads();

    const uint32_t sb = s2u(smem) + 1024;

    const __half* Bw = routed ? g_d + (size_t)ez * I * H : g_sd;
    const __half* Ah = g_acth + (size_t)ez * T * I;
    const __half* Al = g_actl + (size_t)ez * T * I;

    const int u4 = tid & 3;
    const int rb = tid >> 2;
    const int slot0 = m0 + rb;
    const int slot1 = m0 + rb + 64;
    const size_t aO0 = (size_t)(slot0 < cnt ? slot0 : 0) * I + u4 * 8;
    const size_t aO1 = (size_t)(slot1 < cnt ? slot1 : 0) * I + u4 * 8;
    const uint32_t sz0 = (slot0 < cnt) ? 16u : 0u;
    const uint32_t sz1 = (slot1 < cnt) ? 16u : 0u;
    const uint32_t dA0 = SWZ64(rb * 64 + u4 * 16);
    const uint32_t dA1 = SWZ64((rb + 64) * 64 + u4 * 16);
    const int u8 = tid & 7;
    const int rbB = tid >> 3;
    const size_t bSrc = (size_t)rbB * H + n0 + u8 * 8;
    const uint32_t dB = SWZ128(rbB * 128 + u8 * 16);

    auto load_stage = [&](int st, int c) {
        const int k0 = c * 32;
        const uint32_t bp = sb + st * DN_STAGE;
        cp16(bp + DN_A_HI + dA0, Ah + aO0 + k0, sz0);
        cp16(bp + DN_A_LO + dA0, Al + aO0 + k0, sz0);
        cp16(bp + DN_A_HI + dA1, Ah + aO1 + k0, sz1);
        cp16(bp + DN_A_LO + dA1, Al + aO1 + k0, sz1);
        size_t bo = bSrc + (size_t)k0 * H;
        cp16(bp + DN_B + dB, Bw + bo, 16);
    };

    float acc[4][2][4];
#pragma unroll
    for (int i = 0; i < 4; i++)
#pragma unroll
        for (int j = 0; j < 2; j++)
#pragma unroll
            for (int q = 0; q < 4; q++) acc[i][j][q] = 0.f;

    const int mw = (wid & 1) * 64;
    const int nw = (wid >> 1) * 16;
    const int arow_off = ((lane >> 3) & 1) * 8 + (lane & 7);
    const int akb_off = (lane >> 4) * 16;
    const int kloc = (lane & 7) + ((lane >> 3) & 1) * 8;
    const int noff = (lane >> 4) * 8;

    uint32_t aoff[4][2], boff[2];
#pragma unroll
    for (int i = 0; i < 4; i++)
#pragma unroll
        for (int kk = 0; kk < 2; kk++)
            aoff[i][kk] = SWZ64((mw + i * 16 + arow_off) * 64 + kk * 32 + akb_off);
#pragma unroll
    for (int kk = 0; kk < 2; kk++)
        boff[kk] = SWZ128((kk * 16 + kloc) * 128 + (nw + noff) * 2);

    auto compute_stage = [&](int st, bool doLoad, int lstage, int lc) {
        const uint32_t bp = sb + st * DN_STAGE;
#pragma unroll
        for (int kk = 0; kk < 2; kk++) {
            uint32_t a[4][4];
            uint32_t bb[4];
            ldsm_x4t(bb[0], bb[1], bb[2], bb[3], bp + DN_B + boff[kk]);
#pragma unroll
            for (int i = 0; i < 4; i++)
                ldsm_x4(a[i][0], a[i][1], a[i][2], a[i][3], bp + DN_A_HI + aoff[i][kk]);
            if (kk == 0 && doLoad) { load_stage(lstage, lc); CP_COMMIT(); }
#pragma unroll
            for (int i = 0; i < 4; i++) {
                mma_f16(acc[i][0], a[i], bb[0], bb[1]);
                mma_f16(acc[i][1], a[i], bb[2], bb[3]);
            }
#pragma unroll
            for (int i = 0; i < 4; i++)
                ldsm_x4(a[i][0], a[i][1], a[i][2], a[i][3], bp + DN_A_LO + aoff[i][kk]);
#pragma unroll
            for (int i = 0; i < 4; i++) {
                mma_f16(acc[i][0], a[i], bb[0], bb[1]);
                mma_f16(acc[i][1], a[i], bb[2], bb[3]);
            }
        }
    };

    const int NC = I / 32;
    load_stage(0, 0); CP_COMMIT();
    load_stage(1, 1); CP_COMMIT();
    int st = 0;
    for (int c = 0; c < NC; c++) {
        if (c < NC - 1) CP_WAIT1(); else CP_WAIT0();
        __syncthreads();
        int ls = st + 2; if (ls >= 3) ls -= 3;
        compute_stage(st, c + 2 < NC, ls, c + 2);
        if (++st == 3) st = 0;
    }

    const int r4 = lane >> 2;
    const int cp2 = (lane & 3) * 2;
#pragma unroll
    for (int i = 0; i < 4; i++)
#pragma unroll
        for (int hh = 0; hh < 2; hh++) {
            int row = mw + i * 16 + r4 + hh * 8;
            int slot = m0 + row;
            if (slot >= cnt) continue;
            int tok = tokSm[row];
            float w = wSm[row];
            float* dst = out + (size_t)tok * H;
#pragma unroll
            for (int j = 0; j < 2; j++) {
                int col = n0 + nw + j * 8 + cp2;
                atomicAdd(&dst[col],     w * acc[i][j][hh * 2 + 0]);
                atomicAdd(&dst[col + 1], w * acc[i][j][hh * 2 + 1]);
            }
        }
}

// ======================= launch =============================================
extern "C" void kernel_launch(void* const* d_in, const int* in_sizes, int n_in,
                              void* d_out, int out_size) {
    const float* x   = (const float*)d_in[0];
    const float* rw  = (const float*)d_in[1];
    const float* gw  = (const float*)d_in[2];
    const float* uw  = (const float*)d_in[3];
    const float* dw  = (const float*)d_in[4];
    const float* sgw = (const float*)d_in[5];
    const float* suw = (const float*)d_in[6];
    const float* sdw = (const float*)d_in[7];
    float* out = (float*)d_out;

    cudaFuncSetAttribute(mm_gateup_kernel,
                         cudaFuncAttributeMaxDynamicSharedMemorySize, GU_SMEM);
    cudaFuncSetAttribute(mm_down_kernel,
                         cudaFuncAttributeMaxDynamicSharedMemorySize, DN_SMEM);

    init_kernel<<<1, 32>>>();
    prep_kernel<<<NROUTER + NWBLK, 256>>>(x, rw, gw, uw, dw, sgw, suw, sdw, out);
    mm_gateup_kernel<<<dim3(I / 64, T / 128, E + 1), 256, GU_SMEM>>>();
    mm_down_kernel<<<dim3(H / 64, T / 128, E + 1), 256, DN_SMEM>>>(out);
    finalize_kernel<<<1, 32>>>(out);
}

// round 9
// speedup vs baseline: 1.4190x; 1.0551x over previous
#include <cuda_runtime.h>
#include <cuda_fp16.h>
#include <math.h>
#include <stdint.h>

#define H 1024
#define I 2048
#define E 8
#define TOPK 2
#define T 4096   // B*S

// ======================= scratch (static device globals) =====================
__device__ __align__(256) int   g_counts[E];
__device__ __align__(256) float g_probsum[E];
__device__ float g_zsum;
__device__ __align__(256) int   g_list[E * T];
__device__ __align__(256) float g_wlist[E * T];

__device__ __align__(256) __half g_xh[(size_t)T * H];
__device__ __align__(256) __half g_xl[(size_t)T * H];
__device__ __align__(256) __half g_g[(size_t)E * H * I];
__device__ __align__(256) __half g_u[(size_t)E * H * I];
__device__ __align__(256) __half g_d[(size_t)E * I * H];
__device__ __align__(256) __half g_sg[(size_t)H * I];
__device__ __align__(256) __half g_su[(size_t)H * I];
__device__ __align__(256) __half g_sd[(size_t)I * H];
__device__ __align__(256) __half g_acth[(size_t)(E + 1) * T * I];
__device__ __align__(256) __half g_actl[(size_t)(E + 1) * T * I];

// ======================= PTX helpers ========================================
static __device__ __forceinline__ uint32_t s2u(const void* p) {
    uint32_t a;
    asm("{ .reg .u64 t; cvta.to.shared.u64 t, %1; cvt.u32.u64 %0, t; }"
        : "=r"(a) : "l"(p));
    return a;
}
static __device__ __forceinline__ void ldsm_x4(uint32_t& r0, uint32_t& r1,
                                               uint32_t& r2, uint32_t& r3,
                                               uint32_t addr) {
    asm volatile("ldmatrix.sync.aligned.m8n8.x4.shared.b16 {%0,%1,%2,%3}, [%4];"
                 : "=r"(r0), "=r"(r1), "=r"(r2), "=r"(r3) : "r"(addr));
}
static __device__ __forceinline__ void ldsm_x4t(uint32_t& r0, uint32_t& r1,
                                                uint32_t& r2, uint32_t& r3,
                                                uint32_t addr) {
    asm volatile("ldmatrix.sync.aligned.m8n8.x4.trans.shared.b16 {%0,%1,%2,%3}, [%4];"
                 : "=r"(r0), "=r"(r1), "=r"(r2), "=r"(r3) : "r"(addr));
}
static __device__ __forceinline__ void mma_f16(float* c, const uint32_t* a,
                                               uint32_t b0, uint32_t b1) {
    asm volatile(
        "mma.sync.aligned.m16n8k16.row.col.f32.f16.f16.f32 "
        "{%0,%1,%2,%3}, {%4,%5,%6,%7}, {%8,%9}, {%0,%1,%2,%3};"
        : "+f"(c[0]), "+f"(c[1]), "+f"(c[2]), "+f"(c[3])
        : "r"(a[0]), "r"(a[1]), "r"(a[2]), "r"(a[3]), "r"(b0), "r"(b1));
}
static __device__ __forceinline__ void cp16(uint32_t dst, const void* src,
                                            uint32_t sz) {
    asm volatile("cp.async.cg.shared.global [%0], [%1], 16, %2;"
                 :: "r"(dst), "l"(src), "r"(sz) : "memory");
}
static __device__ __forceinline__ void red_add_v2(float* p, float v0, float v1) {
    asm volatile("red.global.add.v2.f32 [%0], {%1, %2};"
                 :: "l"(p), "f"(v0), "f"(v1) : "memory");
}
#define CP_COMMIT() asm volatile("cp.async.commit_group;" ::: "memory")
#define CP_WAIT2()  asm volatile("cp.async.wait_group 2;" ::: "memory")
#define CP_WAIT1()  asm volatile("cp.async.wait_group 1;" ::: "memory")
#define CP_WAIT0()  asm volatile("cp.async.wait_group 0;" ::: "memory")

#define SWZ64(o)  ((uint32_t)(o) ^ ((((uint32_t)(o)) >> 3) & 0x30u))
#define SWZ128(o) ((uint32_t)(o) ^ ((((uint32_t)(o)) >> 3) & 0x70u))

// ======================= SMEM layouts (per stage) ===========================
// gateup stage 24KB: A_hi 8K | A_lo 8K | Bg 4K | Bu 4K
#define GU_A_HI   0
#define GU_A_LO   8192
#define GU_BG     16384
#define GU_BU     20480
#define GU_STAGE  24576
#define GU_SMEM   (1024 + 4 * GU_STAGE)
// down stage 20KB: A_hi 8K | A_lo 8K | B 4K   (N=64)
#define DN_A_HI   0
#define DN_A_LO   8192
#define DN_B      16384
#define DN_STAGE  20480
#define DN_SMEM   (1024 + 4 * DN_STAGE)

// ======================= init / finalize ====================================
__global__ void init_kernel() {
    int i = threadIdx.x;
    if (i < E) { g_counts[i] = 0; g_probsum[i] = 0.f; }
    if (i == 0) g_zsum = 0.f;
}

__global__ void finalize_kernel(float* __restrict__ out) {
    if (threadIdx.x == 0) {
        float aux = 0.f;
#pragma unroll
        for (int e = 0; e < E; e++) {
            float tpe = (float)g_counts[e] / (float)(TOPK * T);
            float ppe = g_probsum[e] / (float)T;
            aux += tpe * ppe;
        }
        out[(size_t)T * H]     = (float)E * aux;
        out[(size_t)T * H + 1] = g_zsum / (float)T;
    }
}

// ======================= prep ===============================================
static __device__ __forceinline__ void split_store_x(const float4 v,
                                                     __half* dh, __half* dl,
                                                     size_t o) {
    __half h0 = __float2half(v.x), h1 = __float2half(v.y);
    __half h2 = __float2half(v.z), h3 = __float2half(v.w);
    __half2 ha, hb, la, lb;
    ha.x = h0; ha.y = h1; hb.x = h2; hb.y = h3;
    la.x = __float2half(v.x - __half2float(h0));
    la.y = __float2half(v.y - __half2float(h1));
    lb.x = __float2half(v.z - __half2float(h2));
    lb.y = __float2half(v.w - __half2float(h3));
    reinterpret_cast<__half2*>(dh + o)[0] = ha;
    reinterpret_cast<__half2*>(dh + o)[1] = hb;
    reinterpret_cast<__half2*>(dl + o)[0] = la;
    reinterpret_cast<__half2*>(dl + o)[1] = lb;
}
static __device__ __forceinline__ void round_store_w(const float4 v,
                                                     __half* dh, size_t o) {
    __half2 a, b;
    a.x = __float2half(v.x); a.y = __float2half(v.y);
    b.x = __float2half(v.z); b.y = __float2half(v.w);
    reinterpret_cast<__half2*>(dh + o)[0] = a;
    reinterpret_cast<__half2*>(dh + o)[1] = b;
}

#define GW4 ((size_t)E * H * I / 4)      // 4194304
#define SW4 ((size_t)H * I / 4)          // 524288
#define WTOT4 (3 * GW4 + 3 * SW4)        // 14155776
#define NROUTER 512
#define NWBLK (WTOT4 / 512)              // 27648

__global__ void prep_kernel(const float* __restrict__ x,
                            const float* __restrict__ rw,
                            const float* __restrict__ gw,
                            const float* __restrict__ uw,
                            const float* __restrict__ dw,
                            const float* __restrict__ sgw,
                            const float* __restrict__ suw,
                            const float* __restrict__ sdw,
                            float* __restrict__ out) {
    const int b = blockIdx.x;
    const int tid = threadIdx.x;

    if (b >= NROUTER) {
        size_t base = (size_t)(b - NROUTER) * 512 + tid;
#pragma unroll
        for (int r = 0; r < 2; r++) {
            size_t i4 = base + r * 256;
            const float* src; __half* dh; size_t loc;
            if (i4 < GW4)                { src = gw;  dh = g_g;  loc = i4; }
            else if (i4 < 2 * GW4)       { src = uw;  dh = g_u;  loc = i4 - GW4; }
            else if (i4 < 3 * GW4)       { src = dw;  dh = g_d;  loc = i4 - 2 * GW4; }
            else if (i4 < 3 * GW4 + SW4) { src = sgw; dh = g_sg; loc = i4 - 3 * GW4; }
            else if (i4 < 3 * GW4 + 2 * SW4) { src = suw; dh = g_su; loc = i4 - 3 * GW4 - SW4; }
            else                         { src = sdw; dh = g_sd; loc = i4 - 3 * GW4 - 2 * SW4; }
            float4 v = reinterpret_cast<const float4*>(src)[loc];
            round_store_w(v, dh, loc * 4);
        }
        return;
    }

    {
        size_t base = (size_t)b * 2048;
        float4 z4 = make_float4(0.f, 0.f, 0.f, 0.f);
#pragma unroll
        for (int k = 0; k < 8; k++) {
            size_t i4 = base + tid + k * 256;
            float4 v = reinterpret_cast<const float4*>(x)[i4];
            split_store_x(v, g_xh, g_xl, i4 * 4);
            reinterpret_cast<float4*>(out)[i4] = z4;
        }
    }
    int t = b * 8 + (tid >> 5);
    int lane = tid & 31;
    const float* xr = x + (size_t)t * H;
    float* out_logits = out + (size_t)T * H + 2;

    float acc[E];
#pragma unroll
    for (int e = 0; e < E; e++) acc[e] = 0.f;
    for (int h = lane; h < H; h += 32) {
        float xv = xr[h];
        const float4* r4 = reinterpret_cast<const float4*>(rw + (size_t)h * E);
        float4 r0 = r4[0], r1 = r4[1];
        acc[0] += xv * r0.x; acc[1] += xv * r0.y;
        acc[2] += xv * r0.z; acc[3] += xv * r0.w;
        acc[4] += xv * r1.x; acc[5] += xv * r1.y;
        acc[6] += xv * r1.z; acc[7] += xv * r1.w;
    }
#pragma unroll
    for (int e = 0; e < E; e++)
#pragma unroll
        for (int off = 16; off > 0; off >>= 1)
            acc[e] += __shfl_xor_sync(0xffffffffu, acc[e], off);

    if (lane == 0) {
        float m = acc[0];
#pragma unroll
        for (int e = 1; e < E; e++) m = fmaxf(m, acc[e]);
        float p[E], s = 0.f;
#pragma unroll
        for (int e = 0; e < E; e++) { p[e] = expf(acc[e] - m); s += p[e]; }
        float inv = 1.f / s;
#pragma unroll
        for (int e = 0; e < E; e++) out_logits[(size_t)t * E + e] = acc[e];
        float lse = m + logf(s);
        atomicAdd(&g_zsum, lse * lse);
#pragma unroll
        for (int e = 0; e < E; e++) atomicAdd(&g_probsum[e], p[e] * inv);

        int e1 = 0;
#pragma unroll
        for (int e = 1; e < E; e++) if (acc[e] > acc[e1]) e1 = e;
        int e2 = (e1 == 0) ? 1 : 0;
#pragma unroll
        for (int e = 0; e < E; e++) if (e != e1 && acc[e] > acc[e2]) e2 = e;
        float p1 = p[e1] * inv, p2 = p[e2] * inv;
        float wn = 1.f / (p1 + p2);
        int pos1 = atomicAdd(&g_counts[e1], 1);
        g_list[e1 * T + pos1] = t;  g_wlist[e1 * T + pos1] = p1 * wn;
        int pos2 = atomicAdd(&g_counts[e2], 1);
        g_list[e2 * T + pos2] = t;  g_wlist[e2 * T + pos2] = p2 * wn;
    }
}

// ======================= GEMM 1: gate+up (HMMA fp16x2) =======================
// block 128x64, warp grid 4(m)x2(n), warp tile 32x32, 4-stage ring
__global__ void __launch_bounds__(256, 2) mm_gateup_kernel() {
    extern __shared__ char smem[];
    const int e = blockIdx.z;
    const int cnt = (e < E) ? g_counts[e] : T;
    const int m0 = blockIdx.y * 128;
    if (m0 >= cnt) return;
    const int n0 = blockIdx.x * 64;
    const int tid = threadIdx.x;
    const int wid = tid >> 5;
    const int lane = tid & 31;

    int* rowTok = (int*)smem;
    if (tid < 128) {
        int slot = m0 + tid;
        rowTok[tid] = (slot < cnt) ? ((e < E) ? g_list[e * T + slot] : slot) : -1;
    }
    __syncthreads();

    const uint32_t sb = s2u(smem) + 1024;

    const __half* Gw = (e < E) ? g_g + (size_t)e * H * I : g_sg;
    const __half* Uw = (e < E) ? g_u + (size_t)e * H * I : g_su;

    const int u4 = tid & 3;
    const int rb = tid >> 2;
    const int tok0 = rowTok[rb];
    const int tok1 = rowTok[rb + 64];
    const size_t aG0 = (size_t)(tok0 >= 0 ? tok0 : 0) * H + u4 * 8;
    const size_t aG1 = (size_t)(tok1 >= 0 ? tok1 : 0) * H + u4 * 8;
    const uint32_t sz0 = (tok0 >= 0) ? 16u : 0u;
    const uint32_t sz1 = (tok1 >= 0) ? 16u : 0u;
    const uint32_t dA0 = SWZ64(rb * 64 + u4 * 16);
    const uint32_t dA1 = SWZ64((rb + 64) * 64 + u4 * 16);
    const int u8 = tid & 7;
    const int rbB = tid >> 3;
    const size_t bGsrc = (size_t)rbB * I + n0 + u8 * 8;
    const uint32_t dB = SWZ128(rbB * 128 + u8 * 16);

    auto load_stage = [&](int st, int c) {
        const int k0 = c * 32;
        const uint32_t bp = sb + st * GU_STAGE;
        cp16(bp + GU_A_HI + dA0, g_xh + aG0 + k0, sz0);
        cp16(bp + GU_A_LO + dA0, g_xl + aG0 + k0, sz0);
        cp16(bp + GU_A_HI + dA1, g_xh + aG1 + k0, sz1);
        cp16(bp + GU_A_LO + dA1, g_xl + aG1 + k0, sz1);
        size_t bo = bGsrc + (size_t)k0 * I;
        cp16(bp + GU_BG + dB, Gw + bo, 16);
        cp16(bp + GU_BU + dB, Uw + bo, 16);
    };

    float accG[2][4][4], accU[2][4][4];
#pragma unroll
    for (int i = 0; i < 2; i++)
#pragma unroll
        for (int j = 0; j < 4; j++)
#pragma unroll
            for (int q = 0; q < 4; q++) { accG[i][j][q] = 0.f; accU[i][j][q] = 0.f; }

    const int mw = (wid >> 1) * 32;
    const int nw = (wid & 1) * 32;
    const int arow_off = ((lane >> 3) & 1) * 8 + (lane & 7);
    const int akb_off = (lane >> 4) * 16;
    const int kloc = (lane & 7) + ((lane >> 3) & 1) * 8;
    const int noff = (lane >> 4) * 8;

    uint32_t aoff[2][2], boff[2][2];
#pragma unroll
    for (int i = 0; i < 2; i++)
#pragma unroll
        for (int kk = 0; kk < 2; kk++)
            aoff[i][kk] = SWZ64((mw + i * 16 + arow_off) * 64 + kk * 32 + akb_off);
#pragma unroll
    for (int jp = 0; jp < 2; jp++)
#pragma unroll
        for (int kk = 0; kk < 2; kk++)
            boff[jp][kk] = SWZ128((kk * 16 + kloc) * 128 + (nw + jp * 16 + noff) * 2);

    auto compute_stage = [&](int st, bool doLoad, int lstage, int lc) {
        const uint32_t bp = sb + st * GU_STAGE;
#pragma unroll
        for (int kk = 0; kk < 2; kk++) {
            uint32_t a[2][4];
            uint32_t gb[2][4], ub[2][4];
#pragma unroll
            for (int jp = 0; jp < 2; jp++) {
                ldsm_x4t(gb[jp][0], gb[jp][1], gb[jp][2], gb[jp][3], bp + GU_BG + boff[jp][kk]);
                ldsm_x4t(ub[jp][0], ub[jp][1], ub[jp][2], ub[jp][3], bp + GU_BU + boff[jp][kk]);
            }
#pragma unroll
            for (int i = 0; i < 2; i++)
                ldsm_x4(a[i][0], a[i][1], a[i][2], a[i][3], bp + GU_A_HI + aoff[i][kk]);
            if (kk == 0 && doLoad) { load_stage(lstage, lc); CP_COMMIT(); }
#pragma unroll
            for (int i = 0; i < 2; i++)
#pragma unroll
                for (int jp = 0; jp < 2; jp++) {
                    mma_f16(accG[i][jp * 2 + 0], a[i], gb[jp][0], gb[jp][1]);
                    mma_f16(accG[i][jp * 2 + 1], a[i], gb[jp][2], gb[jp][3]);
                    mma_f16(accU[i][jp * 2 + 0], a[i], ub[jp][0], ub[jp][1]);
                    mma_f16(accU[i][jp * 2 + 1], a[i], ub[jp][2], ub[jp][3]);
                }
#pragma unroll
            for (int i = 0; i < 2; i++)
                ldsm_x4(a[i][0], a[i][1], a[i][2], a[i][3], bp + GU_A_LO + aoff[i][kk]);
#pragma unroll
            for (int i = 0; i < 2; i++)
#pragma unroll
                for (int jp = 0; jp < 2; jp++) {
                    mma_f16(accG[i][jp * 2 + 0], a[i], gb[jp][0], gb[jp][1]);
                    mma_f16(accG[i][jp * 2 + 1], a[i], gb[jp][2], gb[jp][3]);
                    mma_f16(accU[i][jp * 2 + 0], a[i], ub[jp][0], ub[jp][1]);
                    mma_f16(accU[i][jp * 2 + 1], a[i], ub[jp][2], ub[jp][3]);
                }
        }
    };

    const int NC = H / 32;  // 32
    load_stage(0, 0); CP_COMMIT();
    load_stage(1, 1); CP_COMMIT();
    load_stage(2, 2); CP_COMMIT();
    int st = 0;
    for (int c = 0; c < NC; c++) {
        if (c <= NC - 3) CP_WAIT2();
        else if (c == NC - 2) CP_WAIT1();
        else CP_WAIT0();
        __syncthreads();
        int ls = (st + 3) & 3;
        compute_stage(st, c + 3 < NC, ls, c + 3);
        st = (st + 1) & 3;
    }

    const int r4 = lane >> 2;
    const int cp2 = (lane & 3) * 2;
#pragma unroll
    for (int i = 0; i < 2; i++)
#pragma unroll
        for (int hh = 0; hh < 2; hh++) {
            int slot = m0 + mw + i * 16 + r4 + hh * 8;
            if (slot >= cnt) continue;
#pragma unroll
            for (int j = 0; j < 4; j++) {
                float g0 = accG[i][j][hh * 2 + 0], g1 = accG[i][j][hh * 2 + 1];
                float u0 = accU[i][j][hh * 2 + 0], u1 = accU[i][j][hh * 2 + 1];
                float v0 = g0 / (1.f + __expf(-g0)) * u0;
                float v1 = g1 / (1.f + __expf(-g1)) * u1;
                __half h0 = __float2half(v0), h1 = __float2half(v1);
                __half2 hp; hp.x = h0; hp.y = h1;
                __half2 lp;
                lp.x = __float2half(v0 - __half2float(h0));
                lp.y = __float2half(v1 - __half2float(h1));
                int coln = nw + (j >> 1) * 16 + (j & 1) * 8 + cp2;
                size_t ai = (size_t)e * T * I + (size_t)slot * I + n0 + coln;
                *reinterpret_cast<__half2*>(g_acth + ai) = hp;
                *reinterpret_cast<__half2*>(g_actl + ai) = lp;
            }
        }
}

// ======================= GEMM 2: down (fused routed+shared, fp16x2) ==========
__global__ void __launch_bounds__(256, 2) mm_down_kernel(float* __restrict__ out) {
    extern __shared__ char smem[];
    const int ez = blockIdx.z;           // 0..7 routed, 8 shared
    const bool routed = (ez < E);
    const int cnt = routed ? g_counts[ez] : T;
    const int m0 = blockIdx.y * 128;
    if (m0 >= cnt) return;
    const int n0 = blockIdx.x * 64;
    const int tid = threadIdx.x;
    const int wid = tid >> 5;
    const int lane = tid & 31;

    int* tokSm = (int*)smem;
    float* wSm = (float*)(smem + 512);
    if (tid < 128) {
        int slot = m0 + tid;
        if (routed) {
            tokSm[tid] = (slot < cnt) ? g_list[ez * T + slot] : 0;
            wSm[tid]   = (slot < cnt) ? g_wlist[ez * T + slot] : 0.f;
        } else {
            tokSm[tid] = slot;
            wSm[tid]   = 1.f;
        }
    }
    __syncthreads();

    const uint32_t sb = s2u(smem) + 1024;

    const __half* Bw = routed ? g_d + (size_t)ez * I * H : g_sd;
    const __half* Ah = g_acth + (size_t)ez * T * I;
    const __half* Al = g_actl + (size_t)ez * T * I;

    const int u4 = tid & 3;
    const int rb = tid >> 2;
    const int slot0 = m0 + rb;
    const int slot1 = m0 + rb + 64;
    const size_t aO0 = (size_t)(slot0 < cnt ? slot0 : 0) * I + u4 * 8;
    const size_t aO1 = (size_t)(slot1 < cnt ? slot1 : 0) * I + u4 * 8;
    const uint32_t sz0 = (slot0 < cnt) ? 16u : 0u;
    const uint32_t sz1 = (slot1 < cnt) ? 16u : 0u;
    const uint32_t dA0 = SWZ64(rb * 64 + u4 * 16);
    const uint32_t dA1 = SWZ64((rb + 64) * 64 + u4 * 16);
    const int u8 = tid & 7;
    const int rbB = tid >> 3;
    const size_t bSrc = (size_t)rbB * H + n0 + u8 * 8;
    const uint32_t dB = SWZ128(rbB * 128 + u8 * 16);

    auto load_stage = [&](int st, int c) {
        const int k0 = c * 32;
        const uint32_t bp = sb + st * DN_STAGE;
        cp16(bp + DN_A_HI + dA0, Ah + aO0 + k0, sz0);
        cp16(bp + DN_A_LO + dA0, Al + aO0 + k0, sz0);
        cp16(bp + DN_A_HI + dA1, Ah + aO1 + k0, sz1);
        cp16(bp + DN_A_LO + dA1, Al + aO1 + k0, sz1);
        size_t bo = bSrc + (size_t)k0 * H;
        cp16(bp + DN_B + dB, Bw + bo, 16);
    };

    float acc[2][4][4];
#pragma unroll
    for (int i = 0; i < 2; i++)
#pragma unroll
        for (int j = 0; j < 4; j++)
#pragma unroll
            for (int q = 0; q < 4; q++) acc[i][j][q] = 0.f;

    const int mw = (wid >> 1) * 32;
    const int nw = (wid & 1) * 32;
    const int arow_off = ((lane >> 3) & 1) * 8 + (lane & 7);
    const int akb_off = (lane >> 4) * 16;
    const int kloc = (lane & 7) + ((lane >> 3) & 1) * 8;
    const int noff = (lane >> 4) * 8;

    uint32_t aoff[2][2], boff[2][2];
#pragma unroll
    for (int i = 0; i < 2; i++)
#pragma unroll
        for (int kk = 0; kk < 2; kk++)
            aoff[i][kk] = SWZ64((mw + i * 16 + arow_off) * 64 + kk * 32 + akb_off);
#pragma unroll
    for (int jp = 0; jp < 2; jp++)
#pragma unroll
        for (int kk = 0; kk < 2; kk++)
            boff[jp][kk] = SWZ128((kk * 16 + kloc) * 128 + (nw + jp * 16 + noff) * 2);

    auto compute_stage = [&](int st, bool doLoad, int lstage, int lc) {
        const uint32_t bp = sb + st * DN_STAGE;
#pragma unroll
        for (int kk = 0; kk < 2; kk++) {
            uint32_t a[2][4];
            uint32_t bb[2][4];
#pragma unroll
            for (int jp = 0; jp < 2; jp++)
                ldsm_x4t(bb[jp][0], bb[jp][1], bb[jp][2], bb[jp][3], bp + DN_B + boff[jp][kk]);
#pragma unroll
            for (int i = 0; i < 2; i++)
                ldsm_x4(a[i][0], a[i][1], a[i][2], a[i][3], bp + DN_A_HI + aoff[i][kk]);
            if (kk == 0 && doLoad) { load_stage(lstage, lc); CP_COMMIT(); }
#pragma unroll
            for (int i = 0; i < 2; i++)
#pragma unroll
                for (int jp = 0; jp < 2; jp++) {
                    mma_f16(acc[i][jp * 2 + 0], a[i], bb[jp][0], bb[jp][1]);
                    mma_f16(acc[i][jp * 2 + 1], a[i], bb[jp][2], bb[jp][3]);
                }
#pragma unroll
            for (int i = 0; i < 2; i++)
                ldsm_x4(a[i][0], a[i][1], a[i][2], a[i][3], bp + DN_A_LO + aoff[i][kk]);
#pragma unroll
            for (int i = 0; i < 2; i++)
#pragma unroll
                for (int jp = 0; jp < 2; jp++) {
                    mma_f16(acc[i][jp * 2 + 0], a[i], bb[jp][0], bb[jp][1]);
                    mma_f16(acc[i][jp * 2 + 1], a[i], bb[jp][2], bb[jp][3]);
                }
        }
    };

    const int NC = I / 32;  // 64
    load_stage(0, 0); CP_COMMIT();
    load_stage(1, 1); CP_COMMIT();
    load_stage(2, 2); CP_COMMIT();
    int st = 0;
    for (int c = 0; c < NC; c++) {
        if (c <= NC - 3) CP_WAIT2();
        else if (c == NC - 2) CP_WAIT1();
        else CP_WAIT0();
        __syncthreads();
        int ls = (st + 3) & 3;
        compute_stage(st, c + 3 < NC, ls, c + 3);
        st = (st + 1) & 3;
    }

    const int r4 = lane >> 2;
    const int cp2 = (lane & 3) * 2;
#pragma unroll
    for (int i = 0; i < 2; i++)
#pragma unroll
        for (int hh = 0; hh < 2; hh++) {
            int row = mw + i * 16 + r4 + hh * 8;
            int slot = m0 + row;
            if (slot >= cnt) continue;
            int tok = tokSm[row];
            float w = wSm[row];
            float* dst = out + (size_t)tok * H;
#pragma unroll
            for (int j = 0; j < 4; j++) {
                int col = n0 + nw + (j >> 1) * 16 + (j & 1) * 8 + cp2;
                red_add_v2(dst + col, w * acc[i][j][hh * 2 + 0],
                                      w * acc[i][j][hh * 2 + 1]);
            }
        }
}

// ======================= launch =============================================
extern "C" void kernel_launch(void* const* d_in, const int* in_sizes, int n_in,
                              void* d_out, int out_size) {
    const float* x   = (const float*)d_in[0];
    const float* rw  = (const float*)d_in[1];
    const float* gw  = (const float*)d_in[2];
    const float* uw  = (const float*)d_in[3];
    const float* dw  = (const float*)d_in[4];
    const float* sgw = (const float*)d_in[5];
    const float* suw = (const float*)d_in[6];
    const float* sdw = (const float*)d_in[7];
    float* out = (float*)d_out;

    cudaFuncSetAttribute(mm_gateup_kernel,
                         cudaFuncAttributeMaxDynamicSharedMemorySize, GU_SMEM);
    cudaFuncSetAttribute(mm_down_kernel,
                         cudaFuncAttributeMaxDynamicSharedMemorySize, DN_SMEM);

    init_kernel<<<1, 32>>>();
    prep_kernel<<<NROUTER + NWBLK, 256>>>(x, rw, gw, uw, dw, sgw, suw, sdw, out);
    mm_gateup_kernel<<<dim3(I / 64, T / 128, E + 1), 256, GU_SMEM>>>();
    mm_down_kernel<<<dim3(H / 64, T / 128, E + 1), 256, DN_SMEM>>>(out);
    finalize_kernel<<<1, 32>>>(out);
}

// round 10
// speedup vs baseline: 1.4255x; 1.0046x over previous
#include <cuda_runtime.h>
#include <cuda_fp16.h>
#include <math.h>
#include <stdint.h>

#define H 1024
#define I 2048
#define E 8
#define TOPK 2
#define T 4096   // B*S

// ======================= scratch (static device globals) =====================
__device__ __align__(256) int   g_counts[E];
__device__ __align__(256) float g_probsum[E];
__device__ float g_zsum;
__device__ __align__(256) int   g_list[E * T];
__device__ __align__(256) float g_wlist[E * T];

__device__ __align__(256) __half g_xh[(size_t)T * H];
__device__ __align__(256) __half g_xl[(size_t)T * H];
__device__ __align__(256) __half g_g[(size_t)E * H * I];
__device__ __align__(256) __half g_u[(size_t)E * H * I];
__device__ __align__(256) __half g_d[(size_t)E * I * H];
__device__ __align__(256) __half g_sg[(size_t)H * I];
__device__ __align__(256) __half g_su[(size_t)H * I];
__device__ __align__(256) __half g_sd[(size_t)I * H];
__device__ __align__(256) __half g_acth[(size_t)(E + 1) * T * I];
__device__ __align__(256) __half g_actl[(size_t)(E + 1) * T * I];

// ======================= PTX helpers ========================================
static __device__ __forceinline__ uint32_t s2u(const void* p) {
    uint32_t a;
    asm("{ .reg .u64 t; cvta.to.shared.u64 t, %1; cvt.u32.u64 %0, t; }"
        : "=r"(a) : "l"(p));
    return a;
}
static __device__ __forceinline__ void ldsm_x4(uint32_t& r0, uint32_t& r1,
                                               uint32_t& r2, uint32_t& r3,
                                               uint32_t addr) {
    asm volatile("ldmatrix.sync.aligned.m8n8.x4.shared.b16 {%0,%1,%2,%3}, [%4];"
                 : "=r"(r0), "=r"(r1), "=r"(r2), "=r"(r3) : "r"(addr));
}
static __device__ __forceinline__ void ldsm_x4t(uint32_t& r0, uint32_t& r1,
                                                uint32_t& r2, uint32_t& r3,
                                                uint32_t addr) {
    asm volatile("ldmatrix.sync.aligned.m8n8.x4.trans.shared.b16 {%0,%1,%2,%3}, [%4];"
                 : "=r"(r0), "=r"(r1), "=r"(r2), "=r"(r3) : "r"(addr));
}
static __device__ __forceinline__ void mma_f16(float* c, const uint32_t* a,
                                               uint32_t b0, uint32_t b1) {
    asm volatile(
        "mma.sync.aligned.m16n8k16.row.col.f32.f16.f16.f32 "
        "{%0,%1,%2,%3}, {%4,%5,%6,%7}, {%8,%9}, {%0,%1,%2,%3};"
        : "+f"(c[0]), "+f"(c[1]), "+f"(c[2]), "+f"(c[3])
        : "r"(a[0]), "r"(a[1]), "r"(a[2]), "r"(a[3]), "r"(b0), "r"(b1));
}
static __device__ __forceinline__ void cp16(uint32_t dst, const void* src,
                                            uint32_t sz) {
    asm volatile("cp.async.cg.shared.global [%0], [%1], 16, %2;"
                 :: "r"(dst), "l"(src), "r"(sz) : "memory");
}
static __device__ __forceinline__ void red_add_v2(float* p, float v0, float v1) {
    asm volatile("red.global.add.v2.f32 [%0], {%1, %2};"
                 :: "l"(p), "f"(v0), "f"(v1) : "memory");
}
#define CP_COMMIT() asm volatile("cp.async.commit_group;" ::: "memory")
#define CP_WAIT2()  asm volatile("cp.async.wait_group 2;" ::: "memory")
#define CP_WAIT1()  asm volatile("cp.async.wait_group 1;" ::: "memory")
#define CP_WAIT0()  asm volatile("cp.async.wait_group 0;" ::: "memory")

#define SWZ64(o)  ((uint32_t)(o) ^ ((((uint32_t)(o)) >> 3) & 0x30u))
#define SWZ128(o) ((uint32_t)(o) ^ ((((uint32_t)(o)) >> 3) & 0x70u))

// ======================= SMEM layouts (per stage) ===========================
#define GU_A_HI   0
#define GU_A_LO   8192
#define GU_BG     16384
#define GU_BU     20480
#define GU_STAGE  24576
#define GU_SMEM   (1024 + 4 * GU_STAGE)
#define DN_A_HI   0
#define DN_A_LO   8192
#define DN_B      16384
#define DN_STAGE  20480
#define DN_SMEM   (1024 + 4 * DN_STAGE)

// ======================= init / finalize ====================================
__global__ void init_kernel() {
    int i = threadIdx.x;
    if (i < E) { g_counts[i] = 0; g_probsum[i] = 0.f; }
    if (i == 0) g_zsum = 0.f;
}

__global__ void finalize_kernel(float* __restrict__ out) {
    if (threadIdx.x == 0) {
        float aux = 0.f;
#pragma unroll
        for (int e = 0; e < E; e++) {
            float tpe = (float)g_counts[e] / (float)(TOPK * T);
            float ppe = g_probsum[e] / (float)T;
            aux += tpe * ppe;
        }
        out[(size_t)T * H]     = (float)E * aux;
        out[(size_t)T * H + 1] = g_zsum / (float)T;
    }
}

// ======================= prep (16B-vectorized stores) ========================
static __device__ __forceinline__ void split8(const float4 a, const float4 b,
                                              __half* dh, __half* dl, size_t o) {
    __half2 h0 = __floats2half2_rn(a.x, a.y);
    __half2 h1 = __floats2half2_rn(a.z, a.w);
    __half2 h2 = __floats2half2_rn(b.x, b.y);
    __half2 h3 = __floats2half2_rn(b.z, b.w);
    float2 f0 = __half22float2(h0), f1 = __half22float2(h1);
    float2 f2 = __half22float2(h2), f3 = __half22float2(h3);
    __half2 l0 = __floats2half2_rn(a.x - f0.x, a.y - f0.y);
    __half2 l1 = __floats2half2_rn(a.z - f1.x, a.w - f1.y);
    __half2 l2 = __floats2half2_rn(b.x - f2.x, b.y - f2.y);
    __half2 l3 = __floats2half2_rn(b.z - f3.x, b.w - f3.y);
    uint4 uh, ul;
    uh.x = *(const uint32_t*)&h0; uh.y = *(const uint32_t*)&h1;
    uh.z = *(const uint32_t*)&h2; uh.w = *(const uint32_t*)&h3;
    ul.x = *(const uint32_t*)&l0; ul.y = *(const uint32_t*)&l1;
    ul.z = *(const uint32_t*)&l2; ul.w = *(const uint32_t*)&l3;
    *reinterpret_cast<uint4*>(dh + o) = uh;
    *reinterpret_cast<uint4*>(dl + o) = ul;
}
static __device__ __forceinline__ void round8(const float4 a, const float4 b,
                                              __half* dh, size_t o) {
    __half2 h0 = __floats2half2_rn(a.x, a.y);
    __half2 h1 = __floats2half2_rn(a.z, a.w);
    __half2 h2 = __floats2half2_rn(b.x, b.y);
    __half2 h3 = __floats2half2_rn(b.z, b.w);
    uint4 uh;
    uh.x = *(const uint32_t*)&h0; uh.y = *(const uint32_t*)&h1;
    uh.z = *(const uint32_t*)&h2; uh.w = *(const uint32_t*)&h3;
    *reinterpret_cast<uint4*>(dh + o) = uh;
}

#define GW8 ((size_t)E * H * I / 8)      // pairs of float4
#define SW8 ((size_t)H * I / 8)
#define WTOT8 (3 * GW8 + 3 * SW8)        // 7077888
#define NROUTER 512
#define NWBLK (WTOT8 / 256)              // 27648

__global__ void prep_kernel(const float* __restrict__ x,
                            const float* __restrict__ rw,
                            const float* __restrict__ gw,
                            const float* __restrict__ uw,
                            const float* __restrict__ dw,
                            const float* __restrict__ sgw,
                            const float* __restrict__ suw,
                            const float* __restrict__ sdw,
                            float* __restrict__ out) {
    const int b = blockIdx.x;
    const int tid = threadIdx.x;

    if (b >= NROUTER) {
        // one float4-PAIR (32B read, 16B store per array) per thread
        size_t p8 = (size_t)(b - NROUTER) * 256 + tid;
        const float* src; __half* dh; size_t loc; bool isW = true;
        if (p8 < GW8)                 { src = gw;  dh = g_g;  loc = p8; }
        else if (p8 < 2 * GW8)        { src = uw;  dh = g_u;  loc = p8 - GW8; }
        else if (p8 < 3 * GW8)        { src = dw;  dh = g_d;  loc = p8 - 2 * GW8; }
        else if (p8 < 3 * GW8 + SW8)  { src = sgw; dh = g_sg; loc = p8 - 3 * GW8; }
        else if (p8 < 3 * GW8 + 2 * SW8) { src = suw; dh = g_su; loc = p8 - 3 * GW8 - SW8; }
        else                          { src = sdw; dh = g_sd; loc = p8 - 3 * GW8 - 2 * SW8; }
        (void)isW;
        float4 v0 = reinterpret_cast<const float4*>(src)[loc * 2];
        float4 v1 = reinterpret_cast<const float4*>(src)[loc * 2 + 1];
        round8(v0, v1, dh, loc * 8);
        return;
    }

    // ---- x-split (pairs) + zero out rows for this block's 8 tokens ----
    {
        size_t base = (size_t)b * 1024;    // pairs per block
        float4 z4 = make_float4(0.f, 0.f, 0.f, 0.f);
#pragma unroll
        for (int k = 0; k < 4; k++) {
            size_t p8 = base + tid + k * 256;
            float4 v0 = reinterpret_cast<const float4*>(x)[p8 * 2];
            float4 v1 = reinterpret_cast<const float4*>(x)[p8 * 2 + 1];
            split8(v0, v1, g_xh, g_xl, p8 * 8);
            reinterpret_cast<float4*>(out)[p8 * 2]     = z4;
            reinterpret_cast<float4*>(out)[p8 * 2 + 1] = z4;
        }
    }
    // ---- router ----
    int t = b * 8 + (tid >> 5);
    int lane = tid & 31;
    const float* xr = x + (size_t)t * H;
    float* out_logits = out + (size_t)T * H + 2;

    float acc[E];
#pragma unroll
    for (int e = 0; e < E; e++) acc[e] = 0.f;
    for (int h = lane; h < H; h += 32) {
        float xv = xr[h];
        const float4* r4 = reinterpret_cast<const float4*>(rw + (size_t)h * E);
        float4 r0 = r4[0], r1 = r4[1];
        acc[0] += xv * r0.x; acc[1] += xv * r0.y;
        acc[2] += xv * r0.z; acc[3] += xv * r0.w;
        acc[4] += xv * r1.x; acc[5] += xv * r1.y;
        acc[6] += xv * r1.z; acc[7] += xv * r1.w;
    }
#pragma unroll
    for (int e = 0; e < E; e++)
#pragma unroll
        for (int off = 16; off > 0; off >>= 1)
            acc[e] += __shfl_xor_sync(0xffffffffu, acc[e], off);

    if (lane == 0) {
        float m = acc[0];
#pragma unroll
        for (int e = 1; e < E; e++) m = fmaxf(m, acc[e]);
        float p[E], s = 0.f;
#pragma unroll
        for (int e = 0; e < E; e++) { p[e] = expf(acc[e] - m); s += p[e]; }
        float inv = 1.f / s;
#pragma unroll
        for (int e = 0; e < E; e++) out_logits[(size_t)t * E + e] = acc[e];
        float lse = m + logf(s);
        atomicAdd(&g_zsum, lse * lse);
#pragma unroll
        for (int e = 0; e < E; e++) atomicAdd(&g_probsum[e], p[e] * inv);

        int e1 = 0;
#pragma unroll
        for (int e = 1; e < E; e++) if (acc[e] > acc[e1]) e1 = e;
        int e2 = (e1 == 0) ? 1 : 0;
#pragma unroll
        for (int e = 0; e < E; e++) if (e != e1 && acc[e] > acc[e2]) e2 = e;
        float p1 = p[e1] * inv, p2 = p[e2] * inv;
        float wn = 1.f / (p1 + p2);
        int pos1 = atomicAdd(&g_counts[e1], 1);
        g_list[e1 * T + pos1] = t;  g_wlist[e1 * T + pos1] = p1 * wn;
        int pos2 = atomicAdd(&g_counts[e2], 1);
        g_list[e2 * T + pos2] = t;  g_wlist[e2 * T + pos2] = p2 * wn;
    }
}

// ======================= GEMM 1: gate+up (HMMA fp16x2) =======================
// block 128x64, warp grid 4(m)x2(n), warp tile 32x32, 4-stage ring
__global__ void __launch_bounds__(256, 2) mm_gateup_kernel() {
    extern __shared__ char smem[];
    const int e = blockIdx.z;
    const int cnt = (e < E) ? g_counts[e] : T;
    const int m0 = blockIdx.y * 128;
    if (m0 >= cnt) return;
    const int n0 = blockIdx.x * 64;
    const int tid = threadIdx.x;
    const int wid = tid >> 5;
    const int lane = tid & 31;

    int* rowTok = (int*)smem;
    if (tid < 128) {
        int slot = m0 + tid;
        rowTok[tid] = (slot < cnt) ? ((e < E) ? g_list[e * T + slot] : slot) : -1;
    }
    __syncthreads();

    const uint32_t sb = s2u(smem) + 1024;

    const __half* Gw = (e < E) ? g_g + (size_t)e * H * I : g_sg;
    const __half* Uw = (e < E) ? g_u + (size_t)e * H * I : g_su;

    const int u4 = tid & 3;
    const int rb = tid >> 2;
    const int tok0 = rowTok[rb];
    const int tok1 = rowTok[rb + 64];
    const size_t aG0 = (size_t)(tok0 >= 0 ? tok0 : 0) * H + u4 * 8;
    const size_t aG1 = (size_t)(tok1 >= 0 ? tok1 : 0) * H + u4 * 8;
    const uint32_t sz0 = (tok0 >= 0) ? 16u : 0u;
    const uint32_t sz1 = (tok1 >= 0) ? 16u : 0u;
    const uint32_t dA0 = SWZ64(rb * 64 + u4 * 16);
    const uint32_t dA1 = SWZ64((rb + 64) * 64 + u4 * 16);
    const int u8 = tid & 7;
    const int rbB = tid >> 3;
    const size_t bGsrc = (size_t)rbB * I + n0 + u8 * 8;
    const uint32_t dB = SWZ128(rbB * 128 + u8 * 16);

    auto load_stage = [&](int st, int c) {
        const int k0 = c * 32;
        const uint32_t bp = sb + st * GU_STAGE;
        cp16(bp + GU_A_HI + dA0, g_xh + aG0 + k0, sz0);
        cp16(bp + GU_A_LO + dA0, g_xl + aG0 + k0, sz0);
        cp16(bp + GU_A_HI + dA1, g_xh + aG1 + k0, sz1);
        cp16(bp + GU_A_LO + dA1, g_xl + aG1 + k0, sz1);
        size_t bo = bGsrc + (size_t)k0 * I;
        cp16(bp + GU_BG + dB, Gw + bo, 16);
        cp16(bp + GU_BU + dB, Uw + bo, 16);
    };

    float accG[2][4][4], accU[2][4][4];
#pragma unroll
    for (int i = 0; i < 2; i++)
#pragma unroll
        for (int j = 0; j < 4; j++)
#pragma unroll
            for (int q = 0; q < 4; q++) { accG[i][j][q] = 0.f; accU[i][j][q] = 0.f; }

    const int mw = (wid >> 1) * 32;
    const int nw = (wid & 1) * 32;
    const int arow_off = ((lane >> 3) & 1) * 8 + (lane & 7);
    const int akb_off = (lane >> 4) * 16;
    const int kloc = (lane & 7) + ((lane >> 3) & 1) * 8;
    const int noff = (lane >> 4) * 8;

    uint32_t aoff[2][2], boff[2][2];
#pragma unroll
    for (int i = 0; i < 2; i++)
#pragma unroll
        for (int kk = 0; kk < 2; kk++)
            aoff[i][kk] = SWZ64((mw + i * 16 + arow_off) * 64 + kk * 32 + akb_off);
#pragma unroll
    for (int jp = 0; jp < 2; jp++)
#pragma unroll
        for (int kk = 0; kk < 2; kk++)
            boff[jp][kk] = SWZ128((kk * 16 + kloc) * 128 + (nw + jp * 16 + noff) * 2);

    auto compute_stage = [&](int st, bool doLoad, int lstage, int lc) {
        const uint32_t bp = sb + st * GU_STAGE;
#pragma unroll
        for (int kk = 0; kk < 2; kk++) {
            uint32_t a[2][4];
            uint32_t gb[2][4], ub[2][4];
#pragma unroll
            for (int jp = 0; jp < 2; jp++) {
                ldsm_x4t(gb[jp][0], gb[jp][1], gb[jp][2], gb[jp][3], bp + GU_BG + boff[jp][kk]);
                ldsm_x4t(ub[jp][0], ub[jp][1], ub[jp][2], ub[jp][3], bp + GU_BU + boff[jp][kk]);
            }
#pragma unroll
            for (int i = 0; i < 2; i++)
                ldsm_x4(a[i][0], a[i][1], a[i][2], a[i][3], bp + GU_A_HI + aoff[i][kk]);
            if (kk == 0 && doLoad) { load_stage(lstage, lc); CP_COMMIT(); }
#pragma unroll
            for (int i = 0; i < 2; i++)
#pragma unroll
                for (int jp = 0; jp < 2; jp++) {
                    mma_f16(accG[i][jp * 2 + 0], a[i], gb[jp][0], gb[jp][1]);
                    mma_f16(accG[i][jp * 2 + 1], a[i], gb[jp][2], gb[jp][3]);
                    mma_f16(accU[i][jp * 2 + 0], a[i], ub[jp][0], ub[jp][1]);
                    mma_f16(accU[i][jp * 2 + 1], a[i], ub[jp][2], ub[jp][3]);
                }
#pragma unroll
            for (int i = 0; i < 2; i++)
                ldsm_x4(a[i][0], a[i][1], a[i][2], a[i][3], bp + GU_A_LO + aoff[i][kk]);
#pragma unroll
            for (int i = 0; i < 2; i++)
#pragma unroll
                for (int jp = 0; jp < 2; jp++) {
                    mma_f16(accG[i][jp * 2 + 0], a[i], gb[jp][0], gb[jp][1]);
                    mma_f16(accG[i][jp * 2 + 1], a[i], gb[jp][2], gb[jp][3]);
                    mma_f16(accU[i][jp * 2 + 0], a[i], ub[jp][0], ub[jp][1]);
                    mma_f16(accU[i][jp * 2 + 1], a[i], ub[jp][2], ub[jp][3]);
                }
        }
    };

    const int NC = H / 32;  // 32
    load_stage(0, 0); CP_COMMIT();
    load_stage(1, 1); CP_COMMIT();
    load_stage(2, 2); CP_COMMIT();
    int st = 0;
    for (int c = 0; c < NC; c++) {
        if (c <= NC - 3) CP_WAIT2();
        else if (c == NC - 2) CP_WAIT1();
        else CP_WAIT0();
        __syncthreads();
        int ls = (st + 3) & 3;
        compute_stage(st, c + 3 < NC, ls, c + 3);
        st = (st + 1) & 3;
    }

    const int r4 = lane >> 2;
    const int cp2 = (lane & 3) * 2;
#pragma unroll
    for (int i = 0; i < 2; i++)
#pragma unroll
        for (int hh = 0; hh < 2; hh++) {
            int slot = m0 + mw + i * 16 + r4 + hh * 8;
            if (slot >= cnt) continue;
#pragma unroll
            for (int j = 0; j < 4; j++) {
                float g0 = accG[i][j][hh * 2 + 0], g1 = accG[i][j][hh * 2 + 1];
                float u0 = accU[i][j][hh * 2 + 0], u1 = accU[i][j][hh * 2 + 1];
                float v0 = g0 / (1.f + __expf(-g0)) * u0;
                float v1 = g1 / (1.f + __expf(-g1)) * u1;
                __half h0 = __float2half(v0), h1 = __float2half(v1);
                __half2 hp; hp.x = h0; hp.y = h1;
                __half2 lp;
                lp.x = __float2half(v0 - __half2float(h0));
                lp.y = __float2half(v1 - __half2float(h1));
                int coln = nw + (j >> 1) * 16 + (j & 1) * 8 + cp2;
                size_t ai = (size_t)e * T * I + (size_t)slot * I + n0 + coln;
                *reinterpret_cast<__half2*>(g_acth + ai) = hp;
                *reinterpret_cast<__half2*>(g_actl + ai) = lp;
            }
        }
}

// ======================= GEMM 2: down (fused routed+shared, fp16x2) ==========
__global__ void __launch_bounds__(256, 2) mm_down_kernel(float* __restrict__ out) {
    extern __shared__ char smem[];
    const int ez = blockIdx.z;           // 0..7 routed, 8 shared
    const bool routed = (ez < E);
    const int cnt = routed ? g_counts[ez] : T;
    const int m0 = blockIdx.y * 128;
    if (m0 >= cnt) return;
    const int n0 = blockIdx.x * 64;
    const int tid = threadIdx.x;
    const int wid = tid >> 5;
    const int lane = tid & 31;

    int* tokSm = (int*)smem;
    float* wSm = (float*)(smem + 512);
    if (tid < 128) {
        int slot = m0 + tid;
        if (routed) {
            tokSm[tid] = (slot < cnt) ? g_list[ez * T + slot] : 0;
            wSm[tid]   = (slot < cnt) ? g_wlist[ez * T + slot] : 0.f;
        } else {
            tokSm[tid] = slot;
            wSm[tid]   = 1.f;
        }
    }
    __syncthreads();

    const uint32_t sb = s2u(smem) + 1024;

    const __half* Bw = routed ? g_d + (size_t)ez * I * H : g_sd;
    const __half* Ah = g_acth + (size_t)ez * T * I;
    const __half* Al = g_actl + (size_t)ez * T * I;

    const int u4 = tid & 3;
    const int rb = tid >> 2;
    const int slot0 = m0 + rb;
    const int slot1 = m0 + rb + 64;
    const size_t aO0 = (size_t)(slot0 < cnt ? slot0 : 0) * I + u4 * 8;
    const size_t aO1 = (size_t)(slot1 < cnt ? slot1 : 0) * I + u4 * 8;
    const uint32_t sz0 = (slot0 < cnt) ? 16u : 0u;
    const uint32_t sz1 = (slot1 < cnt) ? 16u : 0u;
    const uint32_t dA0 = SWZ64(rb * 64 + u4 * 16);
    const uint32_t dA1 = SWZ64((rb + 64) * 64 + u4 * 16);
    const int u8 = tid & 7;
    const int rbB = tid >> 3;
    const size_t bSrc = (size_t)rbB * H + n0 + u8 * 8;
    const uint32_t dB = SWZ128(rbB * 128 + u8 * 16);

    auto load_stage = [&](int st, int c) {
        const int k0 = c * 32;
        const uint32_t bp = sb + st * DN_STAGE;
        cp16(bp + DN_A_HI + dA0, Ah + aO0 + k0, sz0);
        cp16(bp + DN_A_LO + dA0, Al + aO0 + k0, sz0);
        cp16(bp + DN_A_HI + dA1, Ah + aO1 + k0, sz1);
        cp16(bp + DN_A_LO + dA1, Al + aO1 + k0, sz1);
        size_t bo = bSrc + (size_t)k0 * H;
        cp16(bp + DN_B + dB, Bw + bo, 16);
    };

    float acc[2][4][4];
#pragma unroll
    for (int i = 0; i < 2; i++)
#pragma unroll
        for (int j = 0; j < 4; j++)
#pragma unroll
            for (int q = 0; q < 4; q++) acc[i][j][q] = 0.f;

    const int mw = (wid >> 1) * 32;
    const int nw = (wid & 1) * 32;
    const int arow_off = ((lane >> 3) & 1) * 8 + (lane & 7);
    const int akb_off = (lane >> 4) * 16;
    const int kloc = (lane & 7) + ((lane >> 3) & 1) * 8;
    const int noff = (lane >> 4) * 8;

    uint32_t aoff[2][2], boff[2][2];
#pragma unroll
    for (int i = 0; i < 2; i++)
#pragma unroll
        for (int kk = 0; kk < 2; kk++)
            aoff[i][kk] = SWZ64((mw + i * 16 + arow_off) * 64 + kk * 32 + akb_off);
#pragma unroll
    for (int jp = 0; jp < 2; jp++)
#pragma unroll
        for (int kk = 0; kk < 2; kk++)
            boff[jp][kk] = SWZ128((kk * 16 + kloc) * 128 + (nw + jp * 16 + noff) * 2);

    auto compute_stage = [&](int st, bool doLoad, int lstage, int lc) {
        const uint32_t bp = sb + st * DN_STAGE;
#pragma unroll
        for (int kk = 0; kk < 2; kk++) {
            uint32_t a[2][4];
            uint32_t bb[2][4];
#pragma unroll
            for (int jp = 0; jp < 2; jp++)
                ldsm_x4t(bb[jp][0], bb[jp][1], bb[jp][2], bb[jp][3], bp + DN_B + boff[jp][kk]);
#pragma unroll
            for (int i = 0; i < 2; i++)
                ldsm_x4(a[i][0], a[i][1], a[i][2], a[i][3], bp + DN_A_HI + aoff[i][kk]);
            if (kk == 0 && doLoad) { load_stage(lstage, lc); CP_COMMIT(); }
#pragma unroll
            for (int i = 0; i < 2; i++)
#pragma unroll
                for (int jp = 0; jp < 2; jp++) {
                    mma_f16(acc[i][jp * 2 + 0], a[i], bb[jp][0], bb[jp][1]);
                    mma_f16(acc[i][jp * 2 + 1], a[i], bb[jp][2], bb[jp][3]);
                }
#pragma unroll
            for (int i = 0; i < 2; i++)
                ldsm_x4(a[i][0], a[i][1], a[i][2], a[i][3], bp + DN_A_LO + aoff[i][kk]);
#pragma unroll
            for (int i = 0; i < 2; i++)
#pragma unroll
                for (int jp = 0; jp < 2; jp++) {
                    mma_f16(acc[i][jp * 2 + 0], a[i], bb[jp][0], bb[jp][1]);
                    mma_f16(acc[i][jp * 2 + 1], a[i], bb[jp][2], bb[jp][3]);
                }
        }
    };

    const int NC = I / 32;  // 64
    load_stage(0, 0); CP_COMMIT();
    load_stage(1, 1); CP_COMMIT();
    load_stage(2, 2); CP_COMMIT();
    int st = 0;
    for (int c = 0; c < NC; c++) {
        if (c <= NC - 3) CP_WAIT2();
        else if (c == NC - 2) CP_WAIT1();
        else CP_WAIT0();
        __syncthreads();
        int ls = (st + 3) & 3;
        compute_stage(st, c + 3 < NC, ls, c + 3);
        st = (st + 1) & 3;
    }

    const int r4 = lane >> 2;
    const int cp2 = (lane & 3) * 2;
#pragma unroll
    for (int i = 0; i < 2; i++)
#pragma unroll
        for (int hh = 0; hh < 2; hh++) {
            int row = mw + i * 16 + r4 + hh * 8;
            int slot = m0 + row;
            if (slot >= cnt) continue;
            int tok = tokSm[row];
            float w = wSm[row];
            float* dst = out + (size_t)tok * H;
#pragma unroll
            for (int j = 0; j < 4; j++) {
                int col = n0 + nw + (j >> 1) * 16 + (j & 1) * 8 + cp2;
                red_add_v2(dst + col, w * acc[i][j][hh * 2 + 0],
                                      w * acc[i][j][hh * 2 + 1]);
            }
        }
}

// ======================= launch =============================================
extern "C" void kernel_launch(void* const* d_in, const int* in_sizes, int n_in,
                              void* d_out, int out_size) {
    const float* x   = (const float*)d_in[0];
    const float* rw  = (const float*)d_in[1];
    const float* gw  = (const float*)d_in[2];
    const float* uw  = (const float*)d_in[3];
    const float* dw  = (const float*)d_in[4];
    const float* sgw = (const float*)d_in[5];
    const float* suw = (const float*)d_in[6];
    const float* sdw = (const float*)d_in[7];
    float* out = (float*)d_out;

    cudaFuncSetAttribute(mm_gateup_kernel,
                         cudaFuncAttributeMaxDynamicSharedMemorySize, GU_SMEM);
    cudaFuncSetAttribute(mm_down_kernel,
                         cudaFuncAttributeMaxDynamicSharedMemorySize, DN_SMEM);

    init_kernel<<<1, 32>>>();
    prep_kernel<<<NROUTER + NWBLK, 256>>>(x, rw, gw, uw, dw, sgw, suw, sdw, out);
    // finalize depends only on prep; moved here so mm_gateup sits at the
    // ncu-captured launch index (3) next profile round.
    finalize_kernel<<<1, 32>>>(out);
    mm_gateup_kernel<<<dim3(I / 64, T / 128, E + 1), 256, GU_SMEM>>>();
    mm_down_kernel<<<dim3(H / 64, T / 128, E + 1), 256, DN_SMEM>>>(out);
}

// round 11
// speedup vs baseline: 1.5230x; 1.0684x over previous
#include <cuda_runtime.h>
#include <cuda_fp16.h>
#include <math.h>
#include <stdint.h>

#define H 1024
#define I 2048
#define E 8
#define TOPK 2
#define T 4096   // B*S

// ======================= scratch (static device globals) =====================
__device__ __align__(256) int   g_counts[E];
__device__ __align__(256) float g_probsum[E];
__device__ float g_zsum;
__device__ __align__(256) int   g_list[E * T];
__device__ __align__(256) float g_wlist[E * T];

__device__ __align__(256) __half g_xh[(size_t)T * H];
__device__ __align__(256) __half g_xl[(size_t)T * H];
__device__ __align__(256) __half g_g[(size_t)E * H * I];
__device__ __align__(256) __half g_u[(size_t)E * H * I];
__device__ __align__(256) __half g_d[(size_t)E * I * H];
__device__ __align__(256) __half g_sg[(size_t)H * I];
__device__ __align__(256) __half g_su[(size_t)H * I];
__device__ __align__(256) __half g_sd[(size_t)I * H];
__device__ __align__(256) __half g_acth[(size_t)(E + 1) * T * I];
__device__ __align__(256) __half g_actl[(size_t)(E + 1) * T * I];

// ======================= PTX helpers ========================================
static __device__ __forceinline__ uint32_t s2u(const void* p) {
    uint32_t a;
    asm("{ .reg .u64 t; cvta.to.shared.u64 t, %1; cvt.u32.u64 %0, t; }"
        : "=r"(a) : "l"(p));
    return a;
}
static __device__ __forceinline__ void ldsm_x4(uint32_t& r0, uint32_t& r1,
                                               uint32_t& r2, uint32_t& r3,
                                               uint32_t addr) {
    asm volatile("ldmatrix.sync.aligned.m8n8.x4.shared.b16 {%0,%1,%2,%3}, [%4];"
                 : "=r"(r0), "=r"(r1), "=r"(r2), "=r"(r3) : "r"(addr));
}
static __device__ __forceinline__ void ldsm_x4t(uint32_t& r0, uint32_t& r1,
                                                uint32_t& r2, uint32_t& r3,
                                                uint32_t addr) {
    asm volatile("ldmatrix.sync.aligned.m8n8.x4.trans.shared.b16 {%0,%1,%2,%3}, [%4];"
                 : "=r"(r0), "=r"(r1), "=r"(r2), "=r"(r3) : "r"(addr));
}
static __device__ __forceinline__ void mma_f16(float* c, const uint32_t* a,
                                               uint32_t b0, uint32_t b1) {
    asm volatile(
        "mma.sync.aligned.m16n8k16.row.col.f32.f16.f16.f32 "
        "{%0,%1,%2,%3}, {%4,%5,%6,%7}, {%8,%9}, {%0,%1,%2,%3};"
        : "+f"(c[0]), "+f"(c[1]), "+f"(c[2]), "+f"(c[3])
        : "r"(a[0]), "r"(a[1]), "r"(a[2]), "r"(a[3]), "r"(b0), "r"(b1));
}
static __device__ __forceinline__ void cp16(uint32_t dst, const void* src,
                                            uint32_t sz) {
    asm volatile("cp.async.cg.shared.global [%0], [%1], 16, %2;"
                 :: "r"(dst), "l"(src), "r"(sz) : "memory");
}
static __device__ __forceinline__ void red_add_v2(float* p, float v0, float v1) {
    asm volatile("red.global.add.v2.f32 [%0], {%1, %2};"
                 :: "l"(p), "f"(v0), "f"(v1) : "memory");
}
#define CP_COMMIT() asm volatile("cp.async.commit_group;" ::: "memory")
#define CP_WAIT0()  asm volatile("cp.async.wait_group 0;" ::: "memory")

#define SWZ64(o)  ((uint32_t)(o) ^ ((((uint32_t)(o)) >> 3) & 0x30u))
#define SWZ128(o) ((uint32_t)(o) ^ ((((uint32_t)(o)) >> 3) & 0x70u))

// ======================= SMEM layouts (per stage) ===========================
#define GU_A_HI   0
#define GU_A_LO   8192
#define GU_BG     16384
#define GU_BU     20480
#define GU_STAGE  24576
#define GU_SMEM   (1024 + 4 * GU_STAGE)
#define DN_A_HI   0
#define DN_A_LO   8192
#define DN_B      16384
#define DN_STAGE  20480
#define DN_SMEM   (1024 + 4 * DN_STAGE)

// ======================= init / finalize ====================================
__global__ void init_kernel() {
    int i = threadIdx.x;
    if (i < E) { g_counts[i] = 0; g_probsum[i] = 0.f; }
    if (i == 0) g_zsum = 0.f;
}

__global__ void finalize_kernel(float* __restrict__ out) {
    if (threadIdx.x == 0) {
        float aux = 0.f;
#pragma unroll
        for (int e = 0; e < E; e++) {
            float tpe = (float)g_counts[e] / (float)(TOPK * T);
            float ppe = g_probsum[e] / (float)T;
            aux += tpe * ppe;
        }
        out[(size_t)T * H]     = (float)E * aux;
        out[(size_t)T * H + 1] = g_zsum / (float)T;
    }
}

// ======================= prep (16B-vectorized stores) ========================
static __device__ __forceinline__ void split8(const float4 a, const float4 b,
                                              __half* dh, __half* dl, size_t o) {
    __half2 h0 = __floats2half2_rn(a.x, a.y);
    __half2 h1 = __floats2half2_rn(a.z, a.w);
    __half2 h2 = __floats2half2_rn(b.x, b.y);
    __half2 h3 = __floats2half2_rn(b.z, b.w);
    float2 f0 = __half22float2(h0), f1 = __half22float2(h1);
    float2 f2 = __half22float2(h2), f3 = __half22float2(h3);
    __half2 l0 = __floats2half2_rn(a.x - f0.x, a.y - f0.y);
    __half2 l1 = __floats2half2_rn(a.z - f1.x, a.w - f1.y);
    __half2 l2 = __floats2half2_rn(b.x - f2.x, b.y - f2.y);
    __half2 l3 = __floats2half2_rn(b.z - f3.x, b.w - f3.y);
    uint4 uh, ul;
    uh.x = *(const uint32_t*)&h0; uh.y = *(const uint32_t*)&h1;
    uh.z = *(const uint32_t*)&h2; uh.w = *(const uint32_t*)&h3;
    ul.x = *(const uint32_t*)&l0; ul.y = *(const uint32_t*)&l1;
    ul.z = *(const uint32_t*)&l2; ul.w = *(const uint32_t*)&l3;
    *reinterpret_cast<uint4*>(dh + o) = uh;
    *reinterpret_cast<uint4*>(dl + o) = ul;
}
static __device__ __forceinline__ void round8(const float4 a, const float4 b,
                                              __half* dh, size_t o) {
    __half2 h0 = __floats2half2_rn(a.x, a.y);
    __half2 h1 = __floats2half2_rn(a.z, a.w);
    __half2 h2 = __floats2half2_rn(b.x, b.y);
    __half2 h3 = __floats2half2_rn(b.z, b.w);
    uint4 uh;
    uh.x = *(const uint32_t*)&h0; uh.y = *(const uint32_t*)&h1;
    uh.z = *(const uint32_t*)&h2; uh.w = *(const uint32_t*)&h3;
    *reinterpret_cast<uint4*>(dh + o) = uh;
}

#define GW8 ((size_t)E * H * I / 8)
#define SW8 ((size_t)H * I / 8)
#define WTOT8 (3 * GW8 + 3 * SW8)
#define NROUTER 512
#define NWBLK (WTOT8 / 256)

__global__ void prep_kernel(const float* __restrict__ x,
                            const float* __restrict__ rw,
                            const float* __restrict__ gw,
                            const float* __restrict__ uw,
                            const float* __restrict__ dw,
                            const float* __restrict__ sgw,
                            const float* __restrict__ suw,
                            const float* __restrict__ sdw,
                            float* __restrict__ out) {
    const int b = blockIdx.x;
    const int tid = threadIdx.x;

    if (b >= NROUTER) {
        size_t p8 = (size_t)(b - NROUTER) * 256 + tid;
        const float* src; __half* dh; size_t loc;
        if (p8 < GW8)                 { src = gw;  dh = g_g;  loc = p8; }
        else if (p8 < 2 * GW8)        { src = uw;  dh = g_u;  loc = p8 - GW8; }
        else if (p8 < 3 * GW8)        { src = dw;  dh = g_d;  loc = p8 - 2 * GW8; }
        else if (p8 < 3 * GW8 + SW8)  { src = sgw; dh = g_sg; loc = p8 - 3 * GW8; }
        else if (p8 < 3 * GW8 + 2 * SW8) { src = suw; dh = g_su; loc = p8 - 3 * GW8 - SW8; }
        else                          { src = sdw; dh = g_sd; loc = p8 - 3 * GW8 - 2 * SW8; }
        float4 v0 = reinterpret_cast<const float4*>(src)[loc * 2];
        float4 v1 = reinterpret_cast<const float4*>(src)[loc * 2 + 1];
        round8(v0, v1, dh, loc * 8);
        return;
    }

    {
        size_t base = (size_t)b * 1024;
        float4 z4 = make_float4(0.f, 0.f, 0.f, 0.f);
#pragma unroll
        for (int k = 0; k < 4; k++) {
            size_t p8 = base + tid + k * 256;
            float4 v0 = reinterpret_cast<const float4*>(x)[p8 * 2];
            float4 v1 = reinterpret_cast<const float4*>(x)[p8 * 2 + 1];
            split8(v0, v1, g_xh, g_xl, p8 * 8);
            reinterpret_cast<float4*>(out)[p8 * 2]     = z4;
            reinterpret_cast<float4*>(out)[p8 * 2 + 1] = z4;
        }
    }
    int t = b * 8 + (tid >> 5);
    int lane = tid & 31;
    const float* xr = x + (size_t)t * H;
    float* out_logits = out + (size_t)T * H + 2;

    float acc[E];
#pragma unroll
    for (int e = 0; e < E; e++) acc[e] = 0.f;
    for (int h = lane; h < H; h += 32) {
        float xv = xr[h];
        const float4* r4 = reinterpret_cast<const float4*>(rw + (size_t)h * E);
        float4 r0 = r4[0], r1 = r4[1];
        acc[0] += xv * r0.x; acc[1] += xv * r0.y;
        acc[2] += xv * r0.z; acc[3] += xv * r0.w;
        acc[4] += xv * r1.x; acc[5] += xv * r1.y;
        acc[6] += xv * r1.z; acc[7] += xv * r1.w;
    }
#pragma unroll
    for (int e = 0; e < E; e++)
#pragma unroll
        for (int off = 16; off > 0; off >>= 1)
            acc[e] += __shfl_xor_sync(0xffffffffu, acc[e], off);

    if (lane == 0) {
        float m = acc[0];
#pragma unroll
        for (int e = 1; e < E; e++) m = fmaxf(m, acc[e]);
        float p[E], s = 0.f;
#pragma unroll
        for (int e = 0; e < E; e++) { p[e] = expf(acc[e] - m); s += p[e]; }
        float inv = 1.f / s;
#pragma unroll
        for (int e = 0; e < E; e++) out_logits[(size_t)t * E + e] = acc[e];
        float lse = m + logf(s);
        atomicAdd(&g_zsum, lse * lse);
#pragma unroll
        for (int e = 0; e < E; e++) atomicAdd(&g_probsum[e], p[e] * inv);

        int e1 = 0;
#pragma unroll
        for (int e = 1; e < E; e++) if (acc[e] > acc[e1]) e1 = e;
        int e2 = (e1 == 0) ? 1 : 0;
#pragma unroll
        for (int e = 0; e < E; e++) if (e != e1 && acc[e] > acc[e2]) e2 = e;
        float p1 = p[e1] * inv, p2 = p[e2] * inv;
        float wn = 1.f / (p1 + p2);
        int pos1 = atomicAdd(&g_counts[e1], 1);
        g_list[e1 * T + pos1] = t;  g_wlist[e1 * T + pos1] = p1 * wn;
        int pos2 = atomicAdd(&g_counts[e2], 1);
        g_list[e2 * T + pos2] = t;  g_wlist[e2 * T + pos2] = p2 * wn;
    }
}

// ======================= GEMM 1: gate+up (HMMA fp16x2) =======================
// block 128x64, warp 32x32, 4-stage ring, pair-wise barriers
__global__ void __launch_bounds__(256, 2) mm_gateup_kernel() {
    extern __shared__ char smem[];
    const int e = blockIdx.z;
    const int cnt = (e < E) ? g_counts[e] : T;
    const int m0 = blockIdx.y * 128;
    if (m0 >= cnt) return;
    const int n0 = blockIdx.x * 64;
    const int tid = threadIdx.x;
    const int wid = tid >> 5;
    const int lane = tid & 31;

    int* rowTok = (int*)smem;
    if (tid < 128) {
        int slot = m0 + tid;
        rowTok[tid] = (slot < cnt) ? ((e < E) ? g_list[e * T + slot] : slot) : -1;
    }
    __syncthreads();

    const uint32_t sb = s2u(smem) + 1024;

    const __half* Gw = (e < E) ? g_g + (size_t)e * H * I : g_sg;
    const __half* Uw = (e < E) ? g_u + (size_t)e * H * I : g_su;

    const int u4 = tid & 3;
    const int rb = tid >> 2;
    const int tok0 = rowTok[rb];
    const int tok1 = rowTok[rb + 64];
    const size_t aG0 = (size_t)(tok0 >= 0 ? tok0 : 0) * H + u4 * 8;
    const size_t aG1 = (size_t)(tok1 >= 0 ? tok1 : 0) * H + u4 * 8;
    const uint32_t sz0 = (tok0 >= 0) ? 16u : 0u;
    const uint32_t sz1 = (tok1 >= 0) ? 16u : 0u;
    const uint32_t dA0 = SWZ64(rb * 64 + u4 * 16);
    const uint32_t dA1 = SWZ64((rb + 64) * 64 + u4 * 16);
    const int u8 = tid & 7;
    const int rbB = tid >> 3;
    const size_t bGsrc = (size_t)rbB * I + n0 + u8 * 8;
    const uint32_t dB = SWZ128(rbB * 128 + u8 * 16);

    auto load_stage = [&](int st, int c) {
        const int k0 = c * 32;
        const uint32_t bp = sb + st * GU_STAGE;
        cp16(bp + GU_A_HI + dA0, g_xh + aG0 + k0, sz0);
        cp16(bp + GU_A_LO + dA0, g_xl + aG0 + k0, sz0);
        cp16(bp + GU_A_HI + dA1, g_xh + aG1 + k0, sz1);
        cp16(bp + GU_A_LO + dA1, g_xl + aG1 + k0, sz1);
        size_t bo = bGsrc + (size_t)k0 * I;
        cp16(bp + GU_BG + dB, Gw + bo, 16);
        cp16(bp + GU_BU + dB, Uw + bo, 16);
    };

    float accG[2][4][4], accU[2][4][4];
#pragma unroll
    for (int i = 0; i < 2; i++)
#pragma unroll
        for (int j = 0; j < 4; j++)
#pragma unroll
            for (int q = 0; q < 4; q++) { accG[i][j][q] = 0.f; accU[i][j][q] = 0.f; }

    const int mw = (wid >> 1) * 32;
    const int nw = (wid & 1) * 32;
    const int arow_off = ((lane >> 3) & 1) * 8 + (lane & 7);
    const int akb_off = (lane >> 4) * 16;
    const int kloc = (lane & 7) + ((lane >> 3) & 1) * 8;
    const int noff = (lane >> 4) * 8;

    uint32_t aoff[2][2], boff[2][2];
#pragma unroll
    for (int i = 0; i < 2; i++)
#pragma unroll
        for (int kk = 0; kk < 2; kk++)
            aoff[i][kk] = SWZ64((mw + i * 16 + arow_off) * 64 + kk * 32 + akb_off);
#pragma unroll
    for (int jp = 0; jp < 2; jp++)
#pragma unroll
        for (int kk = 0; kk < 2; kk++)
            boff[jp][kk] = SWZ128((kk * 16 + kloc) * 128 + (nw + jp * 16 + noff) * 2);

    auto compute_stage = [&](int st) {
        const uint32_t bp = sb + st * GU_STAGE;
#pragma unroll
        for (int kk = 0; kk < 2; kk++) {
            uint32_t a[2][4];
            uint32_t gb[2][4], ub[2][4];
#pragma unroll
            for (int jp = 0; jp < 2; jp++) {
                ldsm_x4t(gb[jp][0], gb[jp][1], gb[jp][2], gb[jp][3], bp + GU_BG + boff[jp][kk]);
                ldsm_x4t(ub[jp][0], ub[jp][1], ub[jp][2], ub[jp][3], bp + GU_BU + boff[jp][kk]);
            }
#pragma unroll
            for (int i = 0; i < 2; i++)
                ldsm_x4(a[i][0], a[i][1], a[i][2], a[i][3], bp + GU_A_HI + aoff[i][kk]);
#pragma unroll
            for (int i = 0; i < 2; i++)
#pragma unroll
                for (int jp = 0; jp < 2; jp++) {
                    mma_f16(accG[i][jp * 2 + 0], a[i], gb[jp][0], gb[jp][1]);
                    mma_f16(accG[i][jp * 2 + 1], a[i], gb[jp][2], gb[jp][3]);
                    mma_f16(accU[i][jp * 2 + 0], a[i], ub[jp][0], ub[jp][1]);
                    mma_f16(accU[i][jp * 2 + 1], a[i], ub[jp][2], ub[jp][3]);
                }
#pragma unroll
            for (int i = 0; i < 2; i++)
                ldsm_x4(a[i][0], a[i][1], a[i][2], a[i][3], bp + GU_A_LO + aoff[i][kk]);
#pragma unroll
            for (int i = 0; i < 2; i++)
#pragma unroll
                for (int jp = 0; jp < 2; jp++) {
                    mma_f16(accG[i][jp * 2 + 0], a[i], gb[jp][0], gb[jp][1]);
                    mma_f16(accG[i][jp * 2 + 1], a[i], gb[jp][2], gb[jp][3]);
                    mma_f16(accU[i][jp * 2 + 0], a[i], ub[jp][0], ub[jp][1]);
                    mma_f16(accU[i][jp * 2 + 1], a[i], ub[jp][2], ub[jp][3]);
                }
        }
    };

    const int NC = H / 32;  // 32 chunks, 16 pairs
    load_stage(0, 0); CP_COMMIT();
    load_stage(1, 1); CP_COMMIT();
    for (int c = 0; c < NC; c += 2) {
        CP_WAIT0();
        __syncthreads();
        // loads for c+2, c+3 target stages last READ in the previous pair
        if (c + 2 < NC) { load_stage((c + 2) & 3, c + 2); CP_COMMIT(); }
        compute_stage(c & 3);
        if (c + 3 < NC) { load_stage((c + 3) & 3, c + 3); CP_COMMIT(); }
        compute_stage((c + 1) & 3);
    }

    const int r4 = lane >> 2;
    const int cp2 = (lane & 3) * 2;
#pragma unroll
    for (int i = 0; i < 2; i++)
#pragma unroll
        for (int hh = 0; hh < 2; hh++) {
            int slot = m0 + mw + i * 16 + r4 + hh * 8;
            if (slot >= cnt) continue;
#pragma unroll
            for (int j = 0; j < 4; j++) {
                float g0 = accG[i][j][hh * 2 + 0], g1 = accG[i][j][hh * 2 + 1];
                float u0 = accU[i][j][hh * 2 + 0], u1 = accU[i][j][hh * 2 + 1];
                float v0 = g0 / (1.f + __expf(-g0)) * u0;
                float v1 = g1 / (1.f + __expf(-g1)) * u1;
                __half h0 = __float2half(v0), h1 = __float2half(v1);
                __half2 hp; hp.x = h0; hp.y = h1;
                __half2 lp;
                lp.x = __float2half(v0 - __half2float(h0));
                lp.y = __float2half(v1 - __half2float(h1));
                int coln = nw + (j >> 1) * 16 + (j & 1) * 8 + cp2;
                size_t ai = (size_t)e * T * I + (size_t)slot * I + n0 + coln;
                *reinterpret_cast<__half2*>(g_acth + ai) = hp;
                *reinterpret_cast<__half2*>(g_actl + ai) = lp;
            }
        }
}

// ======================= GEMM 2: down (fused routed+shared, fp16x2) ==========
__global__ void __launch_bounds__(256, 2) mm_down_kernel(float* __restrict__ out) {
    extern __shared__ char smem[];
    const int ez = blockIdx.z;           // 0..7 routed, 8 shared
    const bool routed = (ez < E);
    const int cnt = routed ? g_counts[ez] : T;
    const int m0 = blockIdx.y * 128;
    if (m0 >= cnt) return;
    const int n0 = blockIdx.x * 64;
    const int tid = threadIdx.x;
    const int wid = tid >> 5;
    const int lane = tid & 31;

    int* tokSm = (int*)smem;
    float* wSm = (float*)(smem + 512);
    if (tid < 128) {
        int slot = m0 + tid;
        if (routed) {
            tokSm[tid] = (slot < cnt) ? g_list[ez * T + slot] : 0;
            wSm[tid]   = (slot < cnt) ? g_wlist[ez * T + slot] : 0.f;
        } else {
            tokSm[tid] = slot;
            wSm[tid]   = 1.f;
        }
    }
    __syncthreads();

    const uint32_t sb = s2u(smem) + 1024;

    const __half* Bw = routed ? g_d + (size_t)ez * I * H : g_sd;
    const __half* Ah = g_acth + (size_t)ez * T * I;
    const __half* Al = g_actl + (size_t)ez * T * I;

    const int u4 = tid & 3;
    const int rb = tid >> 2;
    const int slot0 = m0 + rb;
    const int slot1 = m0 + rb + 64;
    const size_t aO0 = (size_t)(slot0 < cnt ? slot0 : 0) * I + u4 * 8;
    const size_t aO1 = (size_t)(slot1 < cnt ? slot1 : 0) * I + u4 * 8;
    const uint32_t sz0 = (slot0 < cnt) ? 16u : 0u;
    const uint32_t sz1 = (slot1 < cnt) ? 16u : 0u;
    const uint32_t dA0 = SWZ64(rb * 64 + u4 * 16);
    const uint32_t dA1 = SWZ64((rb + 64) * 64 + u4 * 16);
    const int u8 = tid & 7;
    const int rbB = tid >> 3;
    const size_t bSrc = (size_t)rbB * H + n0 + u8 * 8;
    const uint32_t dB = SWZ128(rbB * 128 + u8 * 16);

    auto load_stage = [&](int st, int c) {
        const int k0 = c * 32;
        const uint32_t bp = sb + st * DN_STAGE;
        cp16(bp + DN_A_HI + dA0, Ah + aO0 + k0, sz0);
        cp16(bp + DN_A_LO + dA0, Al + aO0 + k0, sz0);
        cp16(bp + DN_A_HI + dA1, Ah + aO1 + k0, sz1);
        cp16(bp + DN_A_LO + dA1, Al + aO1 + k0, sz1);
        size_t bo = bSrc + (size_t)k0 * H;
        cp16(bp + DN_B + dB, Bw + bo, 16);
    };

    float acc[2][4][4];
#pragma unroll
    for (int i = 0; i < 2; i++)
#pragma unroll
        for (int j = 0; j < 4; j++)
#pragma unroll
            for (int q = 0; q < 4; q++) acc[i][j][q] = 0.f;

    const int mw = (wid >> 1) * 32;
    const int nw = (wid & 1) * 32;
    const int arow_off = ((lane >> 3) & 1) * 8 + (lane & 7);
    const int akb_off = (lane >> 4) * 16;
    const int kloc = (lane & 7) + ((lane >> 3) & 1) * 8;
    const int noff = (lane >> 4) * 8;

    uint32_t aoff[2][2], boff[2][2];
#pragma unroll
    for (int i = 0; i < 2; i++)
#pragma unroll
        for (int kk = 0; kk < 2; kk++)
            aoff[i][kk] = SWZ64((mw + i * 16 + arow_off) * 64 + kk * 32 + akb_off);
#pragma unroll
    for (int jp = 0; jp < 2; jp++)
#pragma unroll
        for (int kk = 0; kk < 2; kk++)
            boff[jp][kk] = SWZ128((kk * 16 + kloc) * 128 + (nw + jp * 16 + noff) * 2);

    auto compute_stage = [&](int st) {
        const uint32_t bp = sb + st * DN_STAGE;
#pragma unroll
        for (int kk = 0; kk < 2; kk++) {
            uint32_t a[2][4];
            uint32_t bb[2][4];
#pragma unroll
            for (int jp = 0; jp < 2; jp++)
                ldsm_x4t(bb[jp][0], bb[jp][1], bb[jp][2], bb[jp][3], bp + DN_B + boff[jp][kk]);
#pragma unroll
            for (int i = 0; i < 2; i++)
                ldsm_x4(a[i][0], a[i][1], a[i][2], a[i][3], bp + DN_A_HI + aoff[i][kk]);
#pragma unroll
            for (int i = 0; i < 2; i++)
#pragma unroll
                for (int jp = 0; jp < 2; jp++) {
                    mma_f16(acc[i][jp * 2 + 0], a[i], bb[jp][0], bb[jp][1]);
                    mma_f16(acc[i][jp * 2 + 1], a[i], bb[jp][2], bb[jp][3]);
                }
#pragma unroll
            for (int i = 0; i < 2; i++)
                ldsm_x4(a[i][0], a[i][1], a[i][2], a[i][3], bp + DN_A_LO + aoff[i][kk]);
#pragma unroll
            for (int i = 0; i < 2; i++)
#pragma unroll
                for (int jp = 0; jp < 2; jp++) {
                    mma_f16(acc[i][jp * 2 + 0], a[i], bb[jp][0], bb[jp][1]);
                    mma_f16(acc[i][jp * 2 + 1], a[i], bb[jp][2], bb[jp][3]);
                }
        }
    };

    const int NC = I / 32;  // 64 chunks, 32 pairs
    load_stage(0, 0); CP_COMMIT();
    load_stage(1, 1); CP_COMMIT();
    for (int c = 0; c < NC; c += 2) {
        CP_WAIT0();
        __syncthreads();
        if (c + 2 < NC) { load_stage((c + 2) & 3, c + 2); CP_COMMIT(); }
        compute_stage(c & 3);
        if (c + 3 < NC) { load_stage((c + 3) & 3, c + 3); CP_COMMIT(); }
        compute_stage((c + 1) & 3);
    }

    const int r4 = lane >> 2;
    const int cp2 = (lane & 3) * 2;
#pragma unroll
    for (int i = 0; i < 2; i++)
#pragma unroll
        for (int hh = 0; hh < 2; hh++) {
            int row = mw + i * 16 + r4 + hh * 8;
            int slot = m0 + row;
            if (slot >= cnt) continue;
            int tok = tokSm[row];
            float w = wSm[row];
            float* dst = out + (size_t)tok * H;
#pragma unroll
            for (int j = 0; j < 4; j++) {
                int col = n0 + nw + (j >> 1) * 16 + (j & 1) * 8 + cp2;
                red_add_v2(dst + col, w * acc[i][j][hh * 2 + 0],
                                      w * acc[i][j][hh * 2 + 1]);
            }
        }
}

// ======================= launch =============================================
extern "C" void kernel_launch(void* const* d_in, const int* in_sizes, int n_in,
                              void* d_out, int out_size) {
    const float* x   = (const float*)d_in[0];
    const float* rw  = (const float*)d_in[1];
    const float* gw  = (const float*)d_in[2];
    const float* uw  = (const float*)d_in[3];
    const float* dw  = (const float*)d_in[4];
    const float* sgw = (const float*)d_in[5];
    const float* suw = (const float*)d_in[6];
    const float* sdw = (const float*)d_in[7];
    float* out = (float*)d_out;

    cudaFuncSetAttribute(mm_gateup_kernel,
                         cudaFuncAttributeMaxDynamicSharedMemorySize, GU_SMEM);
    cudaFuncSetAttribute(mm_down_kernel,
                         cudaFuncAttributeMaxDynamicSharedMemorySize, DN_SMEM);

    init_kernel<<<1, 32>>>();
    prep_kernel<<<NROUTER + NWBLK, 256>>>(x, rw, gw, uw, dw, sgw, suw, sdw, out);
    finalize_kernel<<<1, 32>>>(out);
    mm_gateup_kernel<<<dim3(I / 64, T / 128, E + 1), 256, GU_SMEM>>>();
    mm_down_kernel<<<dim3(H / 64, T / 128, E + 1), 256, DN_SMEM>>>(out);
}

// round 12
// speedup vs baseline: 2.3499x; 1.5429x over previous
#include <cuda_runtime.h>
#include <cuda_fp16.h>
#include <math.h>
#include <stdint.h>

#define H 1024
#define I 2048
#define E 8
#define TOPK 2
#define T 4096   // B*S

// ======================= scratch (static device globals) =====================
__device__ __align__(256) int   g_counts[E];
__device__ __align__(256) float g_probsum[E];
__device__ float g_zsum;
__device__ __align__(256) int   g_list[E * T];
__device__ __align__(256) float g_wlist[E * T];

// plain fp16 everywhere (weights, x, activations)
__device__ __align__(256) __half g_xh[(size_t)T * H];
__device__ __align__(256) __half g_g[(size_t)E * H * I];
__device__ __align__(256) __half g_u[(size_t)E * H * I];
__device__ __align__(256) __half g_d[(size_t)E * I * H];
__device__ __align__(256) __half g_sg[(size_t)H * I];
__device__ __align__(256) __half g_su[(size_t)H * I];
__device__ __align__(256) __half g_sd[(size_t)I * H];
__device__ __align__(256) __half g_acth[(size_t)(E + 1) * T * I];

// ======================= PTX helpers ========================================
static __device__ __forceinline__ uint32_t s2u(const void* p) {
    uint32_t a;
    asm("{ .reg .u64 t; cvta.to.shared.u64 t, %1; cvt.u32.u64 %0, t; }"
        : "=r"(a) : "l"(p));
    return a;
}
static __device__ __forceinline__ void ldsm_x4(uint32_t& r0, uint32_t& r1,
                                               uint32_t& r2, uint32_t& r3,
                                               uint32_t addr) {
    asm volatile("ldmatrix.sync.aligned.m8n8.x4.shared.b16 {%0,%1,%2,%3}, [%4];"
                 : "=r"(r0), "=r"(r1), "=r"(r2), "=r"(r3) : "r"(addr));
}
static __device__ __forceinline__ void ldsm_x4t(uint32_t& r0, uint32_t& r1,
                                                uint32_t& r2, uint32_t& r3,
                                                uint32_t addr) {
    asm volatile("ldmatrix.sync.aligned.m8n8.x4.trans.shared.b16 {%0,%1,%2,%3}, [%4];"
                 : "=r"(r0), "=r"(r1), "=r"(r2), "=r"(r3) : "r"(addr));
}
static __device__ __forceinline__ void mma_f16(float* c, const uint32_t* a,
                                               uint32_t b0, uint32_t b1) {
    asm volatile(
        "mma.sync.aligned.m16n8k16.row.col.f32.f16.f16.f32 "
        "{%0,%1,%2,%3}, {%4,%5,%6,%7}, {%8,%9}, {%0,%1,%2,%3};"
        : "+f"(c[0]), "+f"(c[1]), "+f"(c[2]), "+f"(c[3])
        : "r"(a[0]), "r"(a[1]), "r"(a[2]), "r"(a[3]), "r"(b0), "r"(b1));
}
static __device__ __forceinline__ void cp16(uint32_t dst, const void* src,
                                            uint32_t sz) {
    asm volatile("cp.async.cg.shared.global [%0], [%1], 16, %2;"
                 :: "r"(dst), "l"(src), "r"(sz) : "memory");
}
static __device__ __forceinline__ void red_add_v2(float* p, float v0, float v1) {
    asm volatile("red.global.add.v2.f32 [%0], {%1, %2};"
                 :: "l"(p), "f"(v0), "f"(v1) : "memory");
}
#define CP_COMMIT() asm volatile("cp.async.commit_group;" ::: "memory")
#define CP_WAIT0()  asm volatile("cp.async.wait_group 0;" ::: "memory")

#define SWZ64(o)  ((uint32_t)(o) ^ ((((uint32_t)(o)) >> 3) & 0x30u))
#define SWZ128(o) ((uint32_t)(o) ^ ((((uint32_t)(o)) >> 3) & 0x70u))

// ======================= SMEM layouts (per stage) ===========================
// gateup stage 16KB: A 8K | Bg 4K | Bu 4K
#define GU_A      0
#define GU_BG     8192
#define GU_BU     12288
#define GU_STAGE  16384
#define GU_SMEM   (1024 + 4 * GU_STAGE)
// down stage 12KB: A 8K | B 4K
#define DN_A      0
#define DN_B      8192
#define DN_STAGE  12288
#define DN_SMEM   (1024 + 4 * DN_STAGE)

// ======================= init / finalize ====================================
__global__ void init_kernel() {
    int i = threadIdx.x;
    if (i < E) { g_counts[i] = 0; g_probsum[i] = 0.f; }
    if (i == 0) g_zsum = 0.f;
}

__global__ void finalize_kernel(float* __restrict__ out) {
    if (threadIdx.x == 0) {
        float aux = 0.f;
#pragma unroll
        for (int e = 0; e < E; e++) {
            float tpe = (float)g_counts[e] / (float)(TOPK * T);
            float ppe = g_probsum[e] / (float)T;
            aux += tpe * ppe;
        }
        out[(size_t)T * H]     = (float)E * aux;
        out[(size_t)T * H + 1] = g_zsum / (float)T;
    }
}

// ======================= prep (16B-vectorized stores) ========================
static __device__ __forceinline__ void round8(const float4 a, const float4 b,
                                              __half* dh, size_t o) {
    __half2 h0 = __floats2half2_rn(a.x, a.y);
    __half2 h1 = __floats2half2_rn(a.z, a.w);
    __half2 h2 = __floats2half2_rn(b.x, b.y);
    __half2 h3 = __floats2half2_rn(b.z, b.w);
    uint4 uh;
    uh.x = *(const uint32_t*)&h0; uh.y = *(const uint32_t*)&h1;
    uh.z = *(const uint32_t*)&h2; uh.w = *(const uint32_t*)&h3;
    *reinterpret_cast<uint4*>(dh + o) = uh;
}

#define GW8 ((size_t)E * H * I / 8)
#define SW8 ((size_t)H * I / 8)
#define WTOT8 (3 * GW8 + 3 * SW8)
#define NROUTER 512
#define NWBLK (WTOT8 / 256)

__global__ void prep_kernel(const float* __restrict__ x,
                            const float* __restrict__ rw,
                            const float* __restrict__ gw,
                            const float* __restrict__ uw,
                            const float* __restrict__ dw,
                            const float* __restrict__ sgw,
                            const float* __restrict__ suw,
                            const float* __restrict__ sdw,
                            float* __restrict__ out) {
    const int b = blockIdx.x;
    const int tid = threadIdx.x;

    if (b >= NROUTER) {
        size_t p8 = (size_t)(b - NROUTER) * 256 + tid;
        const float* src; __half* dh; size_t loc;
        if (p8 < GW8)                 { src = gw;  dh = g_g;  loc = p8; }
        else if (p8 < 2 * GW8)        { src = uw;  dh = g_u;  loc = p8 - GW8; }
        else if (p8 < 3 * GW8)        { src = dw;  dh = g_d;  loc = p8 - 2 * GW8; }
        else if (p8 < 3 * GW8 + SW8)  { src = sgw; dh = g_sg; loc = p8 - 3 * GW8; }
        else if (p8 < 3 * GW8 + 2 * SW8) { src = suw; dh = g_su; loc = p8 - 3 * GW8 - SW8; }
        else                          { src = sdw; dh = g_sd; loc = p8 - 3 * GW8 - 2 * SW8; }
        float4 v0 = reinterpret_cast<const float4*>(src)[loc * 2];
        float4 v1 = reinterpret_cast<const float4*>(src)[loc * 2 + 1];
        round8(v0, v1, dh, loc * 8);
        return;
    }

    {
        size_t base = (size_t)b * 1024;
        float4 z4 = make_float4(0.f, 0.f, 0.f, 0.f);
#pragma unroll
        for (int k = 0; k < 4; k++) {
            size_t p8 = base + tid + k * 256;
            float4 v0 = reinterpret_cast<const float4*>(x)[p8 * 2];
            float4 v1 = reinterpret_cast<const float4*>(x)[p8 * 2 + 1];
            round8(v0, v1, g_xh, p8 * 8);
            reinterpret_cast<float4*>(out)[p8 * 2]     = z4;
            reinterpret_cast<float4*>(out)[p8 * 2 + 1] = z4;
        }
    }
    int t = b * 8 + (tid >> 5);
    int lane = tid & 31;
    const float* xr = x + (size_t)t * H;
    float* out_logits = out + (size_t)T * H + 2;

    float acc[E];
#pragma unroll
    for (int e = 0; e < E; e++) acc[e] = 0.f;
    for (int h = lane; h < H; h += 32) {
        float xv = xr[h];
        const float4* r4 = reinterpret_cast<const float4*>(rw + (size_t)h * E);
        float4 r0 = r4[0], r1 = r4[1];
        acc[0] += xv * r0.x; acc[1] += xv * r0.y;
        acc[2] += xv * r0.z; acc[3] += xv * r0.w;
        acc[4] += xv * r1.x; acc[5] += xv * r1.y;
        acc[6] += xv * r1.z; acc[7] += xv * r1.w;
    }
#pragma unroll
    for (int e = 0; e < E; e++)
#pragma unroll
        for (int off = 16; off > 0; off >>= 1)
            acc[e] += __shfl_xor_sync(0xffffffffu, acc[e], off);

    if (lane == 0) {
        float m = acc[0];
#pragma unroll
        for (int e = 1; e < E; e++) m = fmaxf(m, acc[e]);
        float p[E], s = 0.f;
#pragma unroll
        for (int e = 0; e < E; e++) { p[e] = expf(acc[e] - m); s += p[e]; }
        float inv = 1.f / s;
#pragma unroll
        for (int e = 0; e < E; e++) out_logits[(size_t)t * E + e] = acc[e];
        float lse = m + logf(s);
        atomicAdd(&g_zsum, lse * lse);
#pragma unroll
        for (int e = 0; e < E; e++) atomicAdd(&g_probsum[e], p[e] * inv);

        int e1 = 0;
#pragma unroll
        for (int e = 1; e < E; e++) if (acc[e] > acc[e1]) e1 = e;
        int e2 = (e1 == 0) ? 1 : 0;
#pragma unroll
        for (int e = 0; e < E; e++) if (e != e1 && acc[e] > acc[e2]) e2 = e;
        float p1 = p[e1] * inv, p2 = p[e2] * inv;
        float wn = 1.f / (p1 + p2);
        int pos1 = atomicAdd(&g_counts[e1], 1);
        g_list[e1 * T + pos1] = t;  g_wlist[e1 * T + pos1] = p1 * wn;
        int pos2 = atomicAdd(&g_counts[e2], 1);
        g_list[e2 * T + pos2] = t;  g_wlist[e2 * T + pos2] = p2 * wn;
    }
}

// ======================= GEMM 1: gate+up (plain fp16 HMMA) ===================
// block 128x64, warp 32x32, 4-stage ring, pair-wise barriers
__global__ void __launch_bounds__(256, 2) mm_gateup_kernel() {
    extern __shared__ char smem[];
    const int e = blockIdx.z;
    const int cnt = (e < E) ? g_counts[e] : T;
    const int m0 = blockIdx.y * 128;
    if (m0 >= cnt) return;
    const int n0 = blockIdx.x * 64;
    const int tid = threadIdx.x;
    const int wid = tid >> 5;
    const int lane = tid & 31;

    int* rowTok = (int*)smem;
    if (tid < 128) {
        int slot = m0 + tid;
        rowTok[tid] = (slot < cnt) ? ((e < E) ? g_list[e * T + slot] : slot) : -1;
    }
    __syncthreads();

    const uint32_t sb = s2u(smem) + 1024;

    const __half* Gw = (e < E) ? g_g + (size_t)e * H * I : g_sg;
    const __half* Uw = (e < E) ? g_u + (size_t)e * H * I : g_su;

    const int u4 = tid & 3;
    const int rb = tid >> 2;
    const int tok0 = rowTok[rb];
    const int tok1 = rowTok[rb + 64];
    const size_t aG0 = (size_t)(tok0 >= 0 ? tok0 : 0) * H + u4 * 8;
    const size_t aG1 = (size_t)(tok1 >= 0 ? tok1 : 0) * H + u4 * 8;
    const uint32_t sz0 = (tok0 >= 0) ? 16u : 0u;
    const uint32_t sz1 = (tok1 >= 0) ? 16u : 0u;
    const uint32_t dA0 = SWZ64(rb * 64 + u4 * 16);
    const uint32_t dA1 = SWZ64((rb + 64) * 64 + u4 * 16);
    const int u8 = tid & 7;
    const int rbB = tid >> 3;
    const size_t bGsrc = (size_t)rbB * I + n0 + u8 * 8;
    const uint32_t dB = SWZ128(rbB * 128 + u8 * 16);

    auto load_stage = [&](int st, int c) {
        const int k0 = c * 32;
        const uint32_t bp = sb + st * GU_STAGE;
        cp16(bp + GU_A + dA0, g_xh + aG0 + k0, sz0);
        cp16(bp + GU_A + dA1, g_xh + aG1 + k0, sz1);
        size_t bo = bGsrc + (size_t)k0 * I;
        cp16(bp + GU_BG + dB, Gw + bo, 16);
        cp16(bp + GU_BU + dB, Uw + bo, 16);
    };

    float accG[2][4][4], accU[2][4][4];
#pragma unroll
    for (int i = 0; i < 2; i++)
#pragma unroll
        for (int j = 0; j < 4; j++)
#pragma unroll
            for (int q = 0; q < 4; q++) { accG[i][j][q] = 0.f; accU[i][j][q] = 0.f; }

    const int mw = (wid >> 1) * 32;
    const int nw = (wid & 1) * 32;
    const int arow_off = ((lane >> 3) & 1) * 8 + (lane & 7);
    const int akb_off = (lane >> 4) * 16;
    const int kloc = (lane & 7) + ((lane >> 3) & 1) * 8;
    const int noff = (lane >> 4) * 8;

    uint32_t aoff[2][2], boff[2][2];
#pragma unroll
    for (int i = 0; i < 2; i++)
#pragma unroll
        for (int kk = 0; kk < 2; kk++)
            aoff[i][kk] = SWZ64((mw + i * 16 + arow_off) * 64 + kk * 32 + akb_off);
#pragma unroll
    for (int jp = 0; jp < 2; jp++)
#pragma unroll
        for (int kk = 0; kk < 2; kk++)
            boff[jp][kk] = SWZ128((kk * 16 + kloc) * 128 + (nw + jp * 16 + noff) * 2);

    auto compute_stage = [&](int st) {
        const uint32_t bp = sb + st * GU_STAGE;
#pragma unroll
        for (int kk = 0; kk < 2; kk++) {
            uint32_t a[2][4];
            uint32_t gb[2][4], ub[2][4];
#pragma unroll
            for (int jp = 0; jp < 2; jp++) {
                ldsm_x4t(gb[jp][0], gb[jp][1], gb[jp][2], gb[jp][3], bp + GU_BG + boff[jp][kk]);
                ldsm_x4t(ub[jp][0], ub[jp][1], ub[jp][2], ub[jp][3], bp + GU_BU + boff[jp][kk]);
            }
#pragma unroll
            for (int i = 0; i < 2; i++)
                ldsm_x4(a[i][0], a[i][1], a[i][2], a[i][3], bp + GU_A + aoff[i][kk]);
#pragma unroll
            for (int i = 0; i < 2; i++)
#pragma unroll
                for (int jp = 0; jp < 2; jp++) {
                    mma_f16(accG[i][jp * 2 + 0], a[i], gb[jp][0], gb[jp][1]);
                    mma_f16(accG[i][jp * 2 + 1], a[i], gb[jp][2], gb[jp][3]);
                    mma_f16(accU[i][jp * 2 + 0], a[i], ub[jp][0], ub[jp][1]);
                    mma_f16(accU[i][jp * 2 + 1], a[i], ub[jp][2], ub[jp][3]);
                }
        }
    };

    const int NC = H / 32;  // 32 chunks, 16 pairs
    load_stage(0, 0); CP_COMMIT();
    load_stage(1, 1); CP_COMMIT();
    for (int c = 0; c < NC; c += 2) {
        CP_WAIT0();
        __syncthreads();
        if (c + 2 < NC) { load_stage((c + 2) & 3, c + 2); CP_COMMIT(); }
        compute_stage(c & 3);
        if (c + 3 < NC) { load_stage((c + 3) & 3, c + 3); CP_COMMIT(); }
        compute_stage((c + 1) & 3);
    }

    const int r4 = lane >> 2;
    const int cp2 = (lane & 3) * 2;
#pragma unroll
    for (int i = 0; i < 2; i++)
#pragma unroll
        for (int hh = 0; hh < 2; hh++) {
            int slot = m0 + mw + i * 16 + r4 + hh * 8;
            if (slot >= cnt) continue;
#pragma unroll
            for (int j = 0; j < 4; j++) {
                float g0 = accG[i][j][hh * 2 + 0], g1 = accG[i][j][hh * 2 + 1];
                float u0 = accU[i][j][hh * 2 + 0], u1 = accU[i][j][hh * 2 + 1];
                float v0 = g0 / (1.f + __expf(-g0)) * u0;
                float v1 = g1 / (1.f + __expf(-g1)) * u1;
                __half2 hp;
                hp.x = __float2half(v0); hp.y = __float2half(v1);
                int coln = nw + (j >> 1) * 16 + (j & 1) * 8 + cp2;
                size_t ai = (size_t)e * T * I + (size_t)slot * I + n0 + coln;
                *reinterpret_cast<__half2*>(g_acth + ai) = hp;
            }
        }
}

// ======================= GEMM 2: down (fused routed+shared, fp16) ============
__global__ void __launch_bounds__(256, 2) mm_down_kernel(float* __restrict__ out) {
    extern __shared__ char smem[];
    const int ez = blockIdx.z;           // 0..7 routed, 8 shared
    const bool routed = (ez < E);
    const int cnt = routed ? g_counts[ez] : T;
    const int m0 = blockIdx.y * 128;
    if (m0 >= cnt) return;
    const int n0 = blockIdx.x * 64;
    const int tid = threadIdx.x;
    const int wid = tid >> 5;
    const int lane = tid & 31;

    int* tokSm = (int*)smem;
    float* wSm = (float*)(smem + 512);
    if (tid < 128) {
        int slot = m0 + tid;
        if (routed) {
            tokSm[tid] = (slot < cnt) ? g_list[ez * T + slot] : 0;
            wSm[tid]   = (slot < cnt) ? g_wlist[ez * T + slot] : 0.f;
        } else {
            tokSm[tid] = slot;
            wSm[tid]   = 1.f;
        }
    }
    __syncthreads();

    const uint32_t sb = s2u(smem) + 1024;

    const __half* Bw = routed ? g_d + (size_t)ez * I * H : g_sd;
    const __half* Ah = g_acth + (size_t)ez * T * I;

    const int u4 = tid & 3;
    const int rb = tid >> 2;
    const int slot0 = m0 + rb;
    const int slot1 = m0 + rb + 64;
    const size_t aO0 = (size_t)(slot0 < cnt ? slot0 : 0) * I + u4 * 8;
    const size_t aO1 = (size_t)(slot1 < cnt ? slot1 : 0) * I + u4 * 8;
    const uint32_t sz0 = (slot0 < cnt) ? 16u : 0u;
    const uint32_t sz1 = (slot1 < cnt) ? 16u : 0u;
    const uint32_t dA0 = SWZ64(rb * 64 + u4 * 16);
    const uint32_t dA1 = SWZ64((rb + 64) * 64 + u4 * 16);
    const int u8 = tid & 7;
    const int rbB = tid >> 3;
    const size_t bSrc = (size_t)rbB * H + n0 + u8 * 8;
    const uint32_t dB = SWZ128(rbB * 128 + u8 * 16);

    auto load_stage = [&](int st, int c) {
        const int k0 = c * 32;
        const uint32_t bp = sb + st * DN_STAGE;
        cp16(bp + DN_A + dA0, Ah + aO0 + k0, sz0);
        cp16(bp + DN_A + dA1, Ah + aO1 + k0, sz1);
        size_t bo = bSrc + (size_t)k0 * H;
        cp16(bp + DN_B + dB, Bw + bo, 16);
    };

    float acc[2][4][4];
#pragma unroll
    for (int i = 0; i < 2; i++)
#pragma unroll
        for (int j = 0; j < 4; j++)
#pragma unroll
            for (int q = 0; q < 4; q++) acc[i][j][q] = 0.f;

    const int mw = (wid >> 1) * 32;
    const int nw = (wid & 1) * 32;
    const int arow_off = ((lane >> 3) & 1) * 8 + (lane & 7);
    const int akb_off = (lane >> 4) * 16;
    const int kloc = (lane & 7) + ((lane >> 3) & 1) * 8;
    const int noff = (lane >> 4) * 8;

    uint32_t aoff[2][2], boff[2][2];
#pragma unroll
    for (int i = 0; i < 2; i++)
#pragma unroll
        for (int kk = 0; kk < 2; kk++)
            aoff[i][kk] = SWZ64((mw + i * 16 + arow_off) * 64 + kk * 32 + akb_off);
#pragma unroll
    for (int jp = 0; jp < 2; jp++)
#pragma unroll
        for (int kk = 0; kk < 2; kk++)
            boff[jp][kk] = SWZ128((kk * 16 + kloc) * 128 + (nw + jp * 16 + noff) * 2);

    auto compute_stage = [&](int st) {
        const uint32_t bp = sb + st * DN_STAGE;
#pragma unroll
        for (int kk = 0; kk < 2; kk++) {
            uint32_t a[2][4];
            uint32_t bb[2][4];
#pragma unroll
            for (int jp = 0; jp < 2; jp++)
                ldsm_x4t(bb[jp][0], bb[jp][1], bb[jp][2], bb[jp][3], bp + DN_B + boff[jp][kk]);
#pragma unroll
            for (int i = 0; i < 2; i++)
                ldsm_x4(a[i][0], a[i][1], a[i][2], a[i][3], bp + DN_A + aoff[i][kk]);
#pragma unroll
            for (int i = 0; i < 2; i++)
#pragma unroll
                for (int jp = 0; jp < 2; jp++) {
                    mma_f16(acc[i][jp * 2 + 0], a[i], bb[jp][0], bb[jp][1]);
                    mma_f16(acc[i][jp * 2 + 1], a[i], bb[jp][2], bb[jp][3]);
                }
        }
    };

    const int NC = I / 32;  // 64 chunks, 32 pairs
    load_stage(0, 0); CP_COMMIT();
    load_stage(1, 1); CP_COMMIT();
    for (int c = 0; c < NC; c += 2) {
        CP_WAIT0();
        __syncthreads();
        if (c + 2 < NC) { load_stage((c + 2) & 3, c + 2); CP_COMMIT(); }
        compute_stage(c & 3);
        if (c + 3 < NC) { load_stage((c + 3) & 3, c + 3); CP_COMMIT(); }
        compute_stage((c + 1) & 3);
    }

    const int r4 = lane >> 2;
    const int cp2 = (lane & 3) * 2;
#pragma unroll
    for (int i = 0; i < 2; i++)
#pragma unroll
        for (int hh = 0; hh < 2; hh++) {
            int row = mw + i * 16 + r4 + hh * 8;
            int slot = m0 + row;
            if (slot >= cnt) continue;
            int tok = tokSm[row];
            float w = wSm[row];
            float* dst = out + (size_t)tok * H;
#pragma unroll
            for (int j = 0; j < 4; j++) {
                int col = n0 + nw + (j >> 1) * 16 + (j & 1) * 8 + cp2;
                red_add_v2(dst + col, w * acc[i][j][hh * 2 + 0],
                                      w * acc[i][j][hh * 2 + 1]);
            }
        }
}

// ======================= launch =============================================
extern "C" void kernel_launch(void* const* d_in, const int* in_sizes, int n_in,
                              void* d_out, int out_size) {
    const float* x   = (const float*)d_in[0];
    const float* rw  = (const float*)d_in[1];
    const float* gw  = (const float*)d_in[2];
    const float* uw  = (const float*)d_in[3];
    const float* dw  = (const float*)d_in[4];
    const float* sgw = (const float*)d_in[5];
    const float* suw = (const float*)d_in[6];
    const float* sdw = (const float*)d_in[7];
    float* out = (float*)d_out;

    cudaFuncSetAttribute(mm_gateup_kernel,
                         cudaFuncAttributeMaxDynamicSharedMemorySize, GU_SMEM);
    cudaFuncSetAttribute(mm_down_kernel,
                         cudaFuncAttributeMaxDynamicSharedMemorySize, DN_SMEM);

    init_kernel<<<1, 32>>>();
    prep_kernel<<<NROUTER + NWBLK, 256>>>(x, rw, gw, uw, dw, sgw, suw, sdw, out);
    finalize_kernel<<<1, 32>>>(out);
    mm_gateup_kernel<<<dim3(I / 64, T / 128, E + 1), 256, GU_SMEM>>>();
    mm_down_kernel<<<dim3(H / 64, T / 128, E + 1), 256, DN_SMEM>>>(out);
}

// round 13
// speedup vs baseline: 2.4678x; 1.0502x over previous
#include <cuda_runtime.h>
#include <cuda_fp16.h>
#include <math.h>
#include <stdint.h>

#define H 1024
#define I 2048
#define E 8
#define TOPK 2
#define T 4096   // B*S

// ======================= scratch (static device globals) =====================
__device__ __align__(256) int   g_counts[E];
__device__ __align__(256) float g_probsum[E];
__device__ float g_zsum;
__device__ __align__(256) int   g_list[E * T];
__device__ __align__(256) float g_wlist[E * T];

__device__ __align__(256) __half g_xh[(size_t)T * H];
__device__ __align__(256) __half g_g[(size_t)E * H * I];
__device__ __align__(256) __half g_u[(size_t)E * H * I];
__device__ __align__(256) __half g_d[(size_t)E * I * H];
__device__ __align__(256) __half g_sg[(size_t)H * I];
__device__ __align__(256) __half g_su[(size_t)H * I];
__device__ __align__(256) __half g_sd[(size_t)I * H];
__device__ __align__(256) __half g_acth[(size_t)(E + 1) * T * I];

// ======================= PTX helpers ========================================
static __device__ __forceinline__ uint32_t s2u(const void* p) {
    uint32_t a;
    asm("{ .reg .u64 t; cvta.to.shared.u64 t, %1; cvt.u32.u64 %0, t; }"
        : "=r"(a) : "l"(p));
    return a;
}
static __device__ __forceinline__ void ldsm_x4(uint32_t& r0, uint32_t& r1,
                                               uint32_t& r2, uint32_t& r3,
                                               uint32_t addr) {
    asm volatile("ldmatrix.sync.aligned.m8n8.x4.shared.b16 {%0,%1,%2,%3}, [%4];"
                 : "=r"(r0), "=r"(r1), "=r"(r2), "=r"(r3) : "r"(addr));
}
static __device__ __forceinline__ void ldsm_x4t(uint32_t& r0, uint32_t& r1,
                                                uint32_t& r2, uint32_t& r3,
                                                uint32_t addr) {
    asm volatile("ldmatrix.sync.aligned.m8n8.x4.trans.shared.b16 {%0,%1,%2,%3}, [%4];"
                 : "=r"(r0), "=r"(r1), "=r"(r2), "=r"(r3) : "r"(addr));
}
static __device__ __forceinline__ void mma_f16(float* c, const uint32_t* a,
                                               uint32_t b0, uint32_t b1) {
    asm volatile(
        "mma.sync.aligned.m16n8k16.row.col.f32.f16.f16.f32 "
        "{%0,%1,%2,%3}, {%4,%5,%6,%7}, {%8,%9}, {%0,%1,%2,%3};"
        : "+f"(c[0]), "+f"(c[1]), "+f"(c[2]), "+f"(c[3])
        : "r"(a[0]), "r"(a[1]), "r"(a[2]), "r"(a[3]), "r"(b0), "r"(b1));
}
static __device__ __forceinline__ void cp16(uint32_t dst, const void* src,
                                            uint32_t sz) {
    asm volatile("cp.async.cg.shared.global [%0], [%1], 16, %2;"
                 :: "r"(dst), "l"(src), "r"(sz) : "memory");
}
static __device__ __forceinline__ void red_add_v2(float* p, float v0, float v1) {
    asm volatile("red.global.add.v2.f32 [%0], {%1, %2};"
                 :: "l"(p), "f"(v0), "f"(v1) : "memory");
}
#define CP_COMMIT() asm volatile("cp.async.commit_group;" ::: "memory")
#define CP_WAIT0()  asm volatile("cp.async.wait_group 0;" ::: "memory")

#define SWZ64(o)  ((uint32_t)(o) ^ ((((uint32_t)(o)) >> 3) & 0x30u))
#define SWZ128(o) ((uint32_t)(o) ^ ((((uint32_t)(o)) >> 3) & 0x70u))

// ======================= SMEM layouts (per stage) ===========================
// gateup stage 16KB: A 8K | Bg 4K | Bu 4K
#define GU_A      0
#define GU_BG     8192
#define GU_BU     12288
#define GU_STAGE  16384
#define GU_SMEM   (1024 + 4 * GU_STAGE)
// down stage 20KB: A 16K (256 rows x 64B) | B 4K   (M=256, N=64)
#define DN_A      0
#define DN_B      16384
#define DN_STAGE  20480
#define DN_SMEM   (2048 + 4 * DN_STAGE)

// ======================= init / finalize ====================================
__global__ void init_kernel() {
    int i = threadIdx.x;
    if (i < E) { g_counts[i] = 0; g_probsum[i] = 0.f; }
    if (i == 0) g_zsum = 0.f;
}

__global__ void finalize_kernel(float* __restrict__ out) {
    if (threadIdx.x == 0) {
        float aux = 0.f;
#pragma unroll
        for (int e = 0; e < E; e++) {
            float tpe = (float)g_counts[e] / (float)(TOPK * T);
            float ppe = g_probsum[e] / (float)T;
            aux += tpe * ppe;
        }
        out[(size_t)T * H]     = (float)E * aux;
        out[(size_t)T * H + 1] = g_zsum / (float)T;
    }
}

// ======================= prep (16B-vectorized stores) ========================
static __device__ __forceinline__ void round8(const float4 a, const float4 b,
                                              __half* dh, size_t o) {
    __half2 h0 = __floats2half2_rn(a.x, a.y);
    __half2 h1 = __floats2half2_rn(a.z, a.w);
    __half2 h2 = __floats2half2_rn(b.x, b.y);
    __half2 h3 = __floats2half2_rn(b.z, b.w);
    uint4 uh;
    uh.x = *(const uint32_t*)&h0; uh.y = *(const uint32_t*)&h1;
    uh.z = *(const uint32_t*)&h2; uh.w = *(const uint32_t*)&h3;
    *reinterpret_cast<uint4*>(dh + o) = uh;
}

#define GW8 ((size_t)E * H * I / 8)
#define SW8 ((size_t)H * I / 8)
#define WTOT8 (3 * GW8 + 3 * SW8)
#define NROUTER 512
#define NWBLK (WTOT8 / 256)

__global__ void prep_kernel(const float* __restrict__ x,
                            const float* __restrict__ rw,
                            const float* __restrict__ gw,
                            const float* __restrict__ uw,
                            const float* __restrict__ dw,
                            const float* __restrict__ sgw,
                            const float* __restrict__ suw,
                            const float* __restrict__ sdw,
                            float* __restrict__ out) {
    const int b = blockIdx.x;
    const int tid = threadIdx.x;

    if (b >= NROUTER) {
        size_t p8 = (size_t)(b - NROUTER) * 256 + tid;
        const float* src; __half* dh; size_t loc;
        if (p8 < GW8)                 { src = gw;  dh = g_g;  loc = p8; }
        else if (p8 < 2 * GW8)        { src = uw;  dh = g_u;  loc = p8 - GW8; }
        else if (p8 < 3 * GW8)        { src = dw;  dh = g_d;  loc = p8 - 2 * GW8; }
        else if (p8 < 3 * GW8 + SW8)  { src = sgw; dh = g_sg; loc = p8 - 3 * GW8; }
        else if (p8 < 3 * GW8 + 2 * SW8) { src = suw; dh = g_su; loc = p8 - 3 * GW8 - SW8; }
        else                          { src = sdw; dh = g_sd; loc = p8 - 3 * GW8 - 2 * SW8; }
        float4 v0 = reinterpret_cast<const float4*>(src)[loc * 2];
        float4 v1 = reinterpret_cast<const float4*>(src)[loc * 2 + 1];
        round8(v0, v1, dh, loc * 8);
        return;
    }

    {
        size_t base = (size_t)b * 1024;
        float4 z4 = make_float4(0.f, 0.f, 0.f, 0.f);
#pragma unroll
        for (int k = 0; k < 4; k++) {
            size_t p8 = base + tid + k * 256;
            float4 v0 = reinterpret_cast<const float4*>(x)[p8 * 2];
            float4 v1 = reinterpret_cast<const float4*>(x)[p8 * 2 + 1];
            round8(v0, v1, g_xh, p8 * 8);
            reinterpret_cast<float4*>(out)[p8 * 2]     = z4;
            reinterpret_cast<float4*>(out)[p8 * 2 + 1] = z4;
        }
    }
    int t = b * 8 + (tid >> 5);
    int lane = tid & 31;
    const float* xr = x + (size_t)t * H;
    float* out_logits = out + (size_t)T * H + 2;

    float acc[E];
#pragma unroll
    for (int e = 0; e < E; e++) acc[e] = 0.f;
    for (int h = lane; h < H; h += 32) {
        float xv = xr[h];
        const float4* r4 = reinterpret_cast<const float4*>(rw + (size_t)h * E);
        float4 r0 = r4[0], r1 = r4[1];
        acc[0] += xv * r0.x; acc[1] += xv * r0.y;
        acc[2] += xv * r0.z; acc[3] += xv * r0.w;
        acc[4] += xv * r1.x; acc[5] += xv * r1.y;
        acc[6] += xv * r1.z; acc[7] += xv * r1.w;
    }
#pragma unroll
    for (int e = 0; e < E; e++)
#pragma unroll
        for (int off = 16; off > 0; off >>= 1)
            acc[e] += __shfl_xor_sync(0xffffffffu, acc[e], off);

    if (lane == 0) {
        float m = acc[0];
#pragma unroll
        for (int e = 1; e < E; e++) m = fmaxf(m, acc[e]);
        float p[E], s = 0.f;
#pragma unroll
        for (int e = 0; e < E; e++) { p[e] = expf(acc[e] - m); s += p[e]; }
        float inv = 1.f / s;
#pragma unroll
        for (int e = 0; e < E; e++) out_logits[(size_t)t * E + e] = acc[e];
        float lse = m + logf(s);
        atomicAdd(&g_zsum, lse * lse);
#pragma unroll
        for (int e = 0; e < E; e++) atomicAdd(&g_probsum[e], p[e] * inv);

        int e1 = 0;
#pragma unroll
        for (int e = 1; e < E; e++) if (acc[e] > acc[e1]) e1 = e;
        int e2 = (e1 == 0) ? 1 : 0;
#pragma unroll
        for (int e = 0; e < E; e++) if (e != e1 && acc[e] > acc[e2]) e2 = e;
        float p1 = p[e1] * inv, p2 = p[e2] * inv;
        float wn = 1.f / (p1 + p2);
        int pos1 = atomicAdd(&g_counts[e1], 1);
        g_list[e1 * T + pos1] = t;  g_wlist[e1 * T + pos1] = p1 * wn;
        int pos2 = atomicAdd(&g_counts[e2], 1);
        g_list[e2 * T + pos2] = t;  g_wlist[e2 * T + pos2] = p2 * wn;
    }
}

// ======================= GEMM 1: gate+up (plain fp16 HMMA) ===================
// block 128x64, warp 32x32, 4-stage ring, pair-wise barriers
__global__ void __launch_bounds__(256, 2) mm_gateup_kernel() {
    extern __shared__ char smem[];
    const int e = blockIdx.z;
    const int cnt = (e < E) ? g_counts[e] : T;
    const int m0 = blockIdx.y * 128;
    if (m0 >= cnt) return;
    const int n0 = blockIdx.x * 64;
    const int tid = threadIdx.x;
    const int wid = tid >> 5;
    const int lane = tid & 31;

    int* rowTok = (int*)smem;
    if (tid < 128) {
        int slot = m0 + tid;
        rowTok[tid] = (slot < cnt) ? ((e < E) ? g_list[e * T + slot] : slot) : -1;
    }
    __syncthreads();

    const uint32_t sb = s2u(smem) + 1024;

    const __half* Gw = (e < E) ? g_g + (size_t)e * H * I : g_sg;
    const __half* Uw = (e < E) ? g_u + (size_t)e * H * I : g_su;

    const int u4 = tid & 3;
    const int rb = tid >> 2;
    const int tok0 = rowTok[rb];
    const int tok1 = rowTok[rb + 64];
    const size_t aG0 = (size_t)(tok0 >= 0 ? tok0 : 0) * H + u4 * 8;
    const size_t aG1 = (size_t)(tok1 >= 0 ? tok1 : 0) * H + u4 * 8;
    const uint32_t sz0 = (tok0 >= 0) ? 16u : 0u;
    const uint32_t sz1 = (tok1 >= 0) ? 16u : 0u;
    const uint32_t dA0 = SWZ64(rb * 64 + u4 * 16);
    const uint32_t dA1 = SWZ64((rb + 64) * 64 + u4 * 16);
    const int u8 = tid & 7;
    const int rbB = tid >> 3;
    const size_t bGsrc = (size_t)rbB * I + n0 + u8 * 8;
    const uint32_t dB = SWZ128(rbB * 128 + u8 * 16);

    auto load_stage = [&](int st, int c) {
        const int k0 = c * 32;
        const uint32_t bp = sb + st * GU_STAGE;
        cp16(bp + GU_A + dA0, g_xh + aG0 + k0, sz0);
        cp16(bp + GU_A + dA1, g_xh + aG1 + k0, sz1);
        size_t bo = bGsrc + (size_t)k0 * I;
        cp16(bp + GU_BG + dB, Gw + bo, 16);
        cp16(bp + GU_BU + dB, Uw + bo, 16);
    };

    float accG[2][4][4], accU[2][4][4];
#pragma unroll
    for (int i = 0; i < 2; i++)
#pragma unroll
        for (int j = 0; j < 4; j++)
#pragma unroll
            for (int q = 0; q < 4; q++) { accG[i][j][q] = 0.f; accU[i][j][q] = 0.f; }

    const int mw = (wid >> 1) * 32;
    const int nw = (wid & 1) * 32;
    const int arow_off = ((lane >> 3) & 1) * 8 + (lane & 7);
    const int akb_off = (lane >> 4) * 16;
    const int kloc = (lane & 7) + ((lane >> 3) & 1) * 8;
    const int noff = (lane >> 4) * 8;

    uint32_t aoff[2][2], boff[2][2];
#pragma unroll
    for (int i = 0; i < 2; i++)
#pragma unroll
        for (int kk = 0; kk < 2; kk++)
            aoff[i][kk] = SWZ64((mw + i * 16 + arow_off) * 64 + kk * 32 + akb_off);
#pragma unroll
    for (int jp = 0; jp < 2; jp++)
#pragma unroll
        for (int kk = 0; kk < 2; kk++)
            boff[jp][kk] = SWZ128((kk * 16 + kloc) * 128 + (nw + jp * 16 + noff) * 2);

    auto compute_stage = [&](int st) {
        const uint32_t bp = sb + st * GU_STAGE;
#pragma unroll
        for (int kk = 0; kk < 2; kk++) {
            uint32_t a[2][4];
            uint32_t gb[2][4], ub[2][4];
#pragma unroll
            for (int jp = 0; jp < 2; jp++) {
                ldsm_x4t(gb[jp][0], gb[jp][1], gb[jp][2], gb[jp][3], bp + GU_BG + boff[jp][kk]);
                ldsm_x4t(ub[jp][0], ub[jp][1], ub[jp][2], ub[jp][3], bp + GU_BU + boff[jp][kk]);
            }
#pragma unroll
            for (int i = 0; i < 2; i++)
                ldsm_x4(a[i][0], a[i][1], a[i][2], a[i][3], bp + GU_A + aoff[i][kk]);
#pragma unroll
            for (int i = 0; i < 2; i++)
#pragma unroll
                for (int jp = 0; jp < 2; jp++) {
                    mma_f16(accG[i][jp * 2 + 0], a[i], gb[jp][0], gb[jp][1]);
                    mma_f16(accG[i][jp * 2 + 1], a[i], gb[jp][2], gb[jp][3]);
                    mma_f16(accU[i][jp * 2 + 0], a[i], ub[jp][0], ub[jp][1]);
                    mma_f16(accU[i][jp * 2 + 1], a[i], ub[jp][2], ub[jp][3]);
                }
        }
    };

    const int NC = H / 32;  // 32 chunks, 16 pairs
    load_stage(0, 0); CP_COMMIT();
    load_stage(1, 1); CP_COMMIT();
    for (int c = 0; c < NC; c += 2) {
        CP_WAIT0();
        __syncthreads();
        if (c + 2 < NC) { load_stage((c + 2) & 3, c + 2); CP_COMMIT(); }
        compute_stage(c & 3);
        if (c + 3 < NC) { load_stage((c + 3) & 3, c + 3); CP_COMMIT(); }
        compute_stage((c + 1) & 3);
    }

    const int r4 = lane >> 2;
    const int cp2 = (lane & 3) * 2;
#pragma unroll
    for (int i = 0; i < 2; i++)
#pragma unroll
        for (int hh = 0; hh < 2; hh++) {
            int slot = m0 + mw + i * 16 + r4 + hh * 8;
            if (slot >= cnt) continue;
#pragma unroll
            for (int j = 0; j < 4; j++) {
                float g0 = accG[i][j][hh * 2 + 0], g1 = accG[i][j][hh * 2 + 1];
                float u0 = accU[i][j][hh * 2 + 0], u1 = accU[i][j][hh * 2 + 1];
                float v0 = g0 / (1.f + __expf(-g0)) * u0;
                float v1 = g1 / (1.f + __expf(-g1)) * u1;
                __half2 hp;
                hp.x = __float2half(v0); hp.y = __float2half(v1);
                int coln = nw + (j >> 1) * 16 + (j & 1) * 8 + cp2;
                size_t ai = (size_t)e * T * I + (size_t)slot * I + n0 + coln;
                *reinterpret_cast<__half2*>(g_acth + ai) = hp;
            }
        }
}

// ======================= GEMM 2: down (fused, M=256, warp 64x32) =============
__global__ void __launch_bounds__(256, 2) mm_down_kernel(float* __restrict__ out) {
    extern __shared__ char smem[];
    const int ez = blockIdx.z;           // 0..7 routed, 8 shared
    const bool routed = (ez < E);
    const int cnt = routed ? g_counts[ez] : T;
    const int m0 = blockIdx.y * 256;
    if (m0 >= cnt) return;
    const int n0 = blockIdx.x * 64;
    const int tid = threadIdx.x;
    const int wid = tid >> 5;
    const int lane = tid & 31;

    int* tokSm = (int*)smem;                 // 256 ints
    float* wSm = (float*)(smem + 1024);      // 256 floats
    {
        int slot = m0 + tid;
        if (routed) {
            tokSm[tid] = (slot < cnt) ? g_list[ez * T + slot] : 0;
            wSm[tid]   = (slot < cnt) ? g_wlist[ez * T + slot] : 0.f;
        } else {
            tokSm[tid] = slot;
            wSm[tid]   = 1.f;
        }
    }
    __syncthreads();

    const uint32_t sb = s2u(smem) + 2048;

    const __half* Bw = routed ? g_d + (size_t)ez * I * H : g_sd;
    const __half* Ah = g_acth + (size_t)ez * T * I;

    const int u4 = tid & 3;
    const int rb = tid >> 2;                 // 0..63
    // A: 4 rows per thread (rb + 64*r)
    size_t aO[4];
    uint32_t szA[4], dA[4];
#pragma unroll
    for (int r = 0; r < 4; r++) {
        int row = rb + r * 64;
        int slot = m0 + row;
        aO[r]  = (size_t)(slot < cnt ? slot : 0) * I + u4 * 8;
        szA[r] = (slot < cnt) ? 16u : 0u;
        dA[r]  = SWZ64(row * 64 + u4 * 16);
    }
    const int u8 = tid & 7;
    const int rbB = tid >> 3;
    const size_t bSrc = (size_t)rbB * H + n0 + u8 * 8;
    const uint32_t dB = SWZ128(rbB * 128 + u8 * 16);

    auto load_stage = [&](int st, int c) {
        const int k0 = c * 32;
        const uint32_t bp = sb + st * DN_STAGE;
#pragma unroll
        for (int r = 0; r < 4; r++)
            cp16(bp + DN_A + dA[r], Ah + aO[r] + k0, szA[r]);
        size_t bo = bSrc + (size_t)k0 * H;
        cp16(bp + DN_B + dB, Bw + bo, 16);
    };

    float acc[4][4][4];
#pragma unroll
    for (int i = 0; i < 4; i++)
#pragma unroll
        for (int j = 0; j < 4; j++)
#pragma unroll
            for (int q = 0; q < 4; q++) acc[i][j][q] = 0.f;

    const int mw = (wid >> 1) * 64;          // 4 m-warps x 64 rows
    const int nw = (wid & 1) * 32;
    const int arow_off = ((lane >> 3) & 1) * 8 + (lane & 7);
    const int akb_off = (lane >> 4) * 16;
    const int kloc = (lane & 7) + ((lane >> 3) & 1) * 8;
    const int noff = (lane >> 4) * 8;

    uint32_t aoff[4][2], boff[2][2];
#pragma unroll
    for (int i = 0; i < 4; i++)
#pragma unroll
        for (int kk = 0; kk < 2; kk++)
            aoff[i][kk] = SWZ64((mw + i * 16 + arow_off) * 64 + kk * 32 + akb_off);
#pragma unroll
    for (int jp = 0; jp < 2; jp++)
#pragma unroll
        for (int kk = 0; kk < 2; kk++)
            boff[jp][kk] = SWZ128((kk * 16 + kloc) * 128 + (nw + jp * 16 + noff) * 2);

    auto compute_stage = [&](int st) {
        const uint32_t bp = sb + st * DN_STAGE;
#pragma unroll
        for (int kk = 0; kk < 2; kk++) {
            uint32_t a[4][4];
            uint32_t bb[2][4];
#pragma unroll
            for (int jp = 0; jp < 2; jp++)
                ldsm_x4t(bb[jp][0], bb[jp][1], bb[jp][2], bb[jp][3], bp + DN_B + boff[jp][kk]);
#pragma unroll
            for (int i = 0; i < 4; i++)
                ldsm_x4(a[i][0], a[i][1], a[i][2], a[i][3], bp + DN_A + aoff[i][kk]);
#pragma unroll
            for (int i = 0; i < 4; i++)
#pragma unroll
                for (int jp = 0; jp < 2; jp++) {
                    mma_f16(acc[i][jp * 2 + 0], a[i], bb[jp][0], bb[jp][1]);
                    mma_f16(acc[i][jp * 2 + 1], a[i], bb[jp][2], bb[jp][3]);
                }
        }
    };

    const int NC = I / 32;  // 64 chunks, 32 pairs
    load_stage(0, 0); CP_COMMIT();
    load_stage(1, 1); CP_COMMIT();
    for (int c = 0; c < NC; c += 2) {
        CP_WAIT0();
        __syncthreads();
        if (c + 2 < NC) { load_stage((c + 2) & 3, c + 2); CP_COMMIT(); }
        compute_stage(c & 3);
        if (c + 3 < NC) { load_stage((c + 3) & 3, c + 3); CP_COMMIT(); }
        compute_stage((c + 1) & 3);
    }

    const int r4 = lane >> 2;
    const int cp2 = (lane & 3) * 2;
#pragma unroll
    for (int i = 0; i < 4; i++)
#pragma unroll
        for (int hh = 0; hh < 2; hh++) {
            int row = mw + i * 16 + r4 + hh * 8;
            int slot = m0 + row;
            if (slot >= cnt) continue;
            int tok = tokSm[row];
            float w = wSm[row];
            float* dst = out + (size_t)tok * H;
#pragma unroll
            for (int j = 0; j < 4; j++) {
                int col = n0 + nw + (j >> 1) * 16 + (j & 1) * 8 + cp2;
                red_add_v2(dst + col, w * acc[i][j][hh * 2 + 0],
                                      w * acc[i][j][hh * 2 + 1]);
            }
        }
}

// ======================= launch =============================================
extern "C" void kernel_launch(void* const* d_in, const int* in_sizes, int n_in,
                              void* d_out, int out_size) {
    const float* x   = (const float*)d_in[0];
    const float* rw  = (const float*)d_in[1];
    const float* gw  = (const float*)d_in[2];
    const float* uw  = (const float*)d_in[3];
    const float* dw  = (const float*)d_in[4];
    const float* sgw = (const float*)d_in[5];
    const float* suw = (const float*)d_in[6];
    const float* sdw = (const float*)d_in[7];
    float* out = (float*)d_out;

    cudaFuncSetAttribute(mm_gateup_kernel,
                         cudaFuncAttributeMaxDynamicSharedMemorySize, GU_SMEM);
    cudaFuncSetAttribute(mm_down_kernel,
                         cudaFuncAttributeMaxDynamicSharedMemorySize, DN_SMEM);

    init_kernel<<<1, 32>>>();
    prep_kernel<<<NROUTER + NWBLK, 256>>>(x, rw, gw, uw, dw, sgw, suw, sdw, out);
    finalize_kernel<<<1, 32>>>(out);
    mm_gateup_kernel<<<dim3(I / 64, T / 128, E + 1), 256, GU_SMEM>>>();
    mm_down_kernel<<<dim3(H / 64, T / 256, E + 1), 256, DN_SMEM>>>(out);
}